// round 2
// baseline (speedup 1.0000x reference)
#include <cuda_runtime.h>

#define H_ENC 512
#define H_DEC 256
#define VOCAB 8192
#define BATCH 128
#define NTOT  16384
#define LSEQ  13
#define KX    1280           // H_DEC + H_ENC (attended) + H_ENC (h)
#define G4    2048           // 4*H_ENC
#define BV    (BATCH*VOCAB)  // 1048576

// ---------------- device scratch (no cudaMalloc allowed) ----------------
__device__ float g_P[NTOT * H_ENC];       // 32 MB: nh @ W_att2^T + b_att
__device__ float g_h[BATCH * H_ENC];
__device__ float g_c[BATCH * H_ENC];
__device__ int   g_cur[BATCH];
__device__ float g_x[BATCH * KX];         // [emb | attended | h]
__device__ float g_Qh[BATCH * H_ENC];
__device__ float g_score[NTOT];
__device__ float g_gates[BATCH * G4];
__device__ float g_Wg[G4 * KX];           // [W_ih | W_hh] along K
__device__ float g_bg[G4];                // b_ih + b_hh

// ---------------- helpers ----------------
__device__ __forceinline__ unsigned long long pack2(float a) {
    unsigned long long r;
    asm("mov.b64 %0, {%1, %1};" : "=l"(r) : "f"(a));
    return r;
}
__device__ __forceinline__ void ffma2(unsigned long long& d, unsigned long long a,
                                      unsigned long long b) {
    asm("fma.rn.f32x2 %0, %1, %2, %0;" : "+l"(d) : "l"(a), "l"(b));
}
__device__ __forceinline__ float fast_tanh(float x) {
    // 1 - 2/(exp(2x)+1); ~1e-6 rel err, 2 MUFU. Robust at +-inf.
    float e = __expf(2.0f * x);
    float r;
    asm("rcp.approx.f32 %0, %1;" : "=f"(r) : "f"(e + 1.0f));
    return 1.0f - 2.0f * r;
}
__device__ __forceinline__ float sigm(float x) {
    return 1.0f / (1.0f + expf(-x));
}

// ---------------- generic SGEMM: C[M,N] (+bias) (+=) A[M,K] @ W[N,K]^T ----------------
// grid: (M/128, N/64, splits). If ATOMIC, C must be pre-zeroed; split z==0 adds bias.
#define BM  128
#define BN  64
#define BKK 16

template<bool ATOMIC>
__global__ void __launch_bounds__(256) sgemm_kernel(
    const float* __restrict__ A, int lda,
    const float* __restrict__ W, int ldw,
    const float* __restrict__ bias,
    float* __restrict__ C, int ldc,
    int kPerSplit)
{
    __shared__ float As[BKK][132];   // [k][m], padded
    __shared__ float Ws[BKK][68];    // [k][n], padded

    const int tid = threadIdx.x;
    const int rowBase = blockIdx.x * BM;
    const int colBase = blockIdx.y * BN;
    const int kBase0  = blockIdx.z * kPerSplit;
    const int tr = tid >> 3;   // 0..31 -> 4 rows each
    const int tc = tid & 7;    // 0..7  -> 8 cols each (4 f32x2 pairs)

    unsigned long long acc[4][4];
#pragma unroll
    for (int i = 0; i < 4; i++)
#pragma unroll
        for (int j = 0; j < 4; j++) acc[i][j] = 0ull;

    const int aRow = tid >> 2;          // 0..63
    const int kq   = (tid & 3) * 4;
    const int nIters = kPerSplit / BKK;

    for (int ko = 0; ko < nIters; ++ko) {
        const int kb = kBase0 + ko * BKK;
        // load A tile 128x16 (two float4 per thread)
#pragma unroll
        for (int l = 0; l < 2; l++) {
            const int row = aRow + l * 64;
            float4 av = *(const float4*)(A + (size_t)(rowBase + row) * lda + kb + kq);
            As[kq + 0][row] = av.x; As[kq + 1][row] = av.y;
            As[kq + 2][row] = av.z; As[kq + 3][row] = av.w;
        }
        // load W tile 64x16 (one float4 per thread)
        {
            const int row = tid >> 2;   // 0..63
            float4 wv = *(const float4*)(W + (size_t)(colBase + row) * ldw + kb + kq);
            Ws[kq + 0][row] = wv.x; Ws[kq + 1][row] = wv.y;
            Ws[kq + 2][row] = wv.z; Ws[kq + 3][row] = wv.w;
        }
        __syncthreads();
#pragma unroll
        for (int k = 0; k < BKK; k++) {
            float4 av = *(const float4*)&As[k][tr * 4];
            ulonglong2 b0 = *(const ulonglong2*)&Ws[k][tc * 8];
            ulonglong2 b1 = *(const ulonglong2*)&Ws[k][tc * 8 + 4];
            unsigned long long a0 = pack2(av.x), a1 = pack2(av.y);
            unsigned long long a2 = pack2(av.z), a3 = pack2(av.w);
            ffma2(acc[0][0], a0, b0.x); ffma2(acc[0][1], a0, b0.y);
            ffma2(acc[0][2], a0, b1.x); ffma2(acc[0][3], a0, b1.y);
            ffma2(acc[1][0], a1, b0.x); ffma2(acc[1][1], a1, b0.y);
            ffma2(acc[1][2], a1, b1.x); ffma2(acc[1][3], a1, b1.y);
            ffma2(acc[2][0], a2, b0.x); ffma2(acc[2][1], a2, b0.y);
            ffma2(acc[2][2], a2, b1.x); ffma2(acc[2][3], a2, b1.y);
            ffma2(acc[3][0], a3, b0.x); ffma2(acc[3][1], a3, b0.y);
            ffma2(acc[3][2], a3, b1.x); ffma2(acc[3][3], a3, b1.y);
        }
        __syncthreads();
    }

    const int row0 = rowBase + tr * 4;
    const int col0 = colBase + tc * 8;
#pragma unroll
    for (int i = 0; i < 4; i++) {
#pragma unroll
        for (int j = 0; j < 4; j++) {
            union { unsigned long long u; float2 f; } v;
            v.u = acc[i][j];
            const int col = col0 + j * 2;
            if (bias != nullptr && blockIdx.z == 0) {
                v.f.x += bias[col];
                v.f.y += bias[col + 1];
            }
            float* cp = C + (size_t)(row0 + i) * ldc + col;
            if (ATOMIC) {
                atomicAdd(cp, v.f.x);
                atomicAdd(cp + 1, v.f.y);
            } else {
                *(float2*)cp = v.f;
            }
        }
    }
}

// ---------------- setup kernels ----------------
__global__ void __launch_bounds__(256) k_concatW(
    const float* __restrict__ W_ih, const float* __restrict__ W_hh,
    const float* __restrict__ b_ih, const float* __restrict__ b_hh)
{
    const int total = G4 * KX;
    for (int idx = blockIdx.x * blockDim.x + threadIdx.x; idx < total;
         idx += gridDim.x * blockDim.x) {
        int j = idx / KX;
        int k = idx - j * KX;
        g_Wg[idx] = (k < H_DEC + H_ENC) ? W_ih[j * (H_DEC + H_ENC) + k]
                                        : W_hh[j * H_ENC + (k - H_DEC - H_ENC)];
    }
    int gid = blockIdx.x * blockDim.x + threadIdx.x;
    if (gid < G4) g_bg[gid] = b_ih[gid] + b_hh[gid];
}

__global__ void __launch_bounds__(256) k_init_state(
    const float* __restrict__ nh, const int* __restrict__ root,
    const int* __restrict__ labels)
{
    int idx = blockIdx.x * blockDim.x + threadIdx.x;   // 65536
    int b = idx >> 9, j = idx & 511;
    g_h[idx] = nh[(size_t)root[b] * H_ENC + j];
    g_c[idx] = 0.0f;
    if (idx < BATCH) g_cur[idx] = labels[idx];         // labels[0, :]
}

__global__ void __launch_bounds__(256) k_zero_out0(float* __restrict__ out) {
    for (int i = blockIdx.x * blockDim.x + threadIdx.x; i < BV;
         i += gridDim.x * blockDim.x)
        out[i] = 0.0f;
}

// ---------------- per-step kernels ----------------
__global__ void __launch_bounds__(256) k_step_init(const float* __restrict__ emb) {
    int idx = blockIdx.x * blockDim.x + threadIdx.x;   // 262144 = 128*2048
    g_gates[idx] = 0.0f;
    if (idx < BATCH * H_ENC) {
        g_Qh[idx] = 0.0f;
        int b = idx >> 9, j = idx & 511;
        g_x[b * KX + H_DEC + H_ENC + j] = g_h[idx];    // h slot
    }
    if (idx < BATCH * H_DEC) {
        int b = idx >> 8, j = idx & 255;
        g_x[b * KX + j] = emb[(size_t)g_cur[b] * H_DEC + j];   // emb slot
    }
}

// fused: score -> segment softmax -> attended, one block per segment
__global__ void __launch_bounds__(256) k_attention(
    const float* __restrict__ nh, const int* __restrict__ root,
    const float* __restrict__ v_att)
{
    const int b = blockIdx.x;
    const int tid = threadIdx.x, lid = tid & 31, wid = tid >> 5;
    __shared__ float sQ[H_ENC], sV[H_ENC];
    __shared__ float sred[8];
    __shared__ float s_m, s_invz;
    __shared__ float wbuf[256];

    const int s0 = root[b];
    const int s1 = (b == BATCH - 1) ? NTOT : root[b + 1];

    for (int j = tid; j < H_ENC; j += 256) { sQ[j] = g_Qh[b * H_ENC + j]; sV[j] = v_att[j]; }
    __syncthreads();

    // pass 1: score[n] = sum_j v[j] * tanh(P[n,j] + Qh[b,j])   (b_att folded into P)
    const float2* sQ2 = (const float2*)sQ;
    const float2* sV2 = (const float2*)sV;
    for (int n = s0 + wid; n < s1; n += 8) {
        const float2* Pr2 = (const float2*)(g_P + (size_t)n * H_ENC);
        float acc = 0.0f;
#pragma unroll
        for (int it = 0; it < 8; ++it) {
            int j = lid + it * 32;
            float2 p = Pr2[j], q = sQ2[j], vv = sV2[j];
            acc += vv.x * fast_tanh(p.x + q.x) + vv.y * fast_tanh(p.y + q.y);
        }
#pragma unroll
        for (int o = 16; o; o >>= 1) acc += __shfl_xor_sync(0xffffffffu, acc, o);
        if (lid == 0) g_score[n] = acc;
    }
    __syncthreads();

    // pass 2: segment max
    float m = -3.402823466e38f;
    for (int n = s0 + tid; n < s1; n += 256) m = fmaxf(m, g_score[n]);
#pragma unroll
    for (int o = 16; o; o >>= 1) m = fmaxf(m, __shfl_xor_sync(0xffffffffu, m, o));
    if (lid == 0) sred[wid] = m;
    __syncthreads();
    if (tid == 0) {
        float mm = sred[0];
        for (int w = 1; w < 8; w++) mm = fmaxf(mm, sred[w]);
        s_m = mm;
    }
    __syncthreads();
    m = s_m;

    // pass 3: segment sum of exp
    float z = 0.0f;
    for (int n = s0 + tid; n < s1; n += 256) z += expf(g_score[n] - m);
#pragma unroll
    for (int o = 16; o; o >>= 1) z += __shfl_xor_sync(0xffffffffu, z, o);
    if (lid == 0) sred[wid] = z;
    __syncthreads();
    if (tid == 0) {
        float zz = 0.0f;
        for (int w = 0; w < 8; w++) zz += sred[w];
        s_invz = 1.0f / zz;
    }
    __syncthreads();
    const float invz = s_invz;

    // pass 4: attended[b, :] = sum_n w_n * nh[n, :]; thread owns cols (2*tid, 2*tid+1)
    float2 a = make_float2(0.0f, 0.0f);
    for (int cs = s0; cs < s1; cs += 256) {
        const int cn = min(256, s1 - cs);
        __syncthreads();
        if (tid < cn) wbuf[tid] = expf(g_score[cs + tid] - m);
        __syncthreads();
#pragma unroll 4
        for (int i = 0; i < cn; i++) {
            float w = wbuf[i];
            float2 r = *(const float2*)(nh + (size_t)(cs + i) * H_ENC + 2 * tid);
            a.x += w * r.x;
            a.y += w * r.y;
        }
    }
    a.x *= invz; a.y *= invz;
    *(float2*)&g_x[b * KX + H_DEC + 2 * tid] = a;
}

// LSTM elementwise update + zero this step's logits slab (written next by atomic GEMM)
__global__ void __launch_bounds__(256) k_lstm(float* __restrict__ slab) {
    const int idx = blockIdx.x * blockDim.x + threadIdx.x;   // 131072
    for (int i = idx; i < BV; i += 131072) slab[i] = 0.0f;
    if (idx < BATCH * H_ENC) {
        const int b = idx >> 9, j = idx & 511;
        const float* gr = g_gates + b * G4;
        float ig = gr[j], fg = gr[512 + j], gg = gr[1024 + j], og = gr[1536 + j];
        float c = sigm(fg) * g_c[idx] + sigm(ig) * tanhf(gg);
        g_c[idx] = c;
        g_h[idx] = sigm(og) * tanhf(c);
    }
}

__global__ void __launch_bounds__(256) k_argmax(const float* __restrict__ slab) {
    const int b = blockIdx.x, tid = threadIdx.x;
    const float* row = slab + (size_t)b * VOCAB;
    float best = -3.402823466e38f;
    int bi = VOCAB;
    for (int j = tid; j < VOCAB; j += 256) {
        float v = row[j];
        if (v > best) { best = v; bi = j; }   // ascending j -> keeps first max per thread
    }
    __shared__ float sv[256];
    __shared__ int si[256];
    sv[tid] = best; si[tid] = bi;
    __syncthreads();
    for (int s = 128; s; s >>= 1) {
        if (tid < s) {
            float v2 = sv[tid + s]; int i2 = si[tid + s];
            if (v2 > sv[tid] || (v2 == sv[tid] && i2 < si[tid])) { sv[tid] = v2; si[tid] = i2; }
        }
        __syncthreads();
    }
    if (tid == 0) g_cur[b] = si[0];
}

// ---------------- launch ----------------
extern "C" void kernel_launch(void* const* d_in, const int* in_sizes, int n_in,
                              void* d_out, int out_size) {
    const float* nh    = (const float*)d_in[0];
    const int*   labels= (const int*)  d_in[1];
    const int*   root  = (const int*)  d_in[2];
    const float* emb   = (const float*)d_in[3];
    const float* W_att = (const float*)d_in[4];
    const float* b_att = (const float*)d_in[5];
    const float* v_att = (const float*)d_in[6];
    const float* W_ih  = (const float*)d_in[7];
    const float* W_hh  = (const float*)d_in[8];
    const float* b_ih  = (const float*)d_in[9];
    const float* b_hh  = (const float*)d_in[10];
    const float* W_out = (const float*)d_in[11];
    const float* b_out = (const float*)d_in[12];
    float* out = (float*)d_out;

    float *pP, *pH, *pQh, *pX, *pWg, *pBg, *pGates;
    cudaGetSymbolAddress((void**)&pP, g_P);
    cudaGetSymbolAddress((void**)&pH, g_h);
    cudaGetSymbolAddress((void**)&pQh, g_Qh);
    cudaGetSymbolAddress((void**)&pX, g_x);
    cudaGetSymbolAddress((void**)&pWg, g_Wg);
    cudaGetSymbolAddress((void**)&pBg, g_bg);
    cudaGetSymbolAddress((void**)&pGates, g_gates);

    // ---- setup (inside graph; runs every replay, deterministic) ----
    k_concatW<<<1280, 256>>>(W_ih, W_hh, b_ih, b_hh);
    // P = nh @ W_att[:,512:]^T + b_att   (step-invariant)
    sgemm_kernel<false><<<dim3(NTOT / BM, H_ENC / BN, 1), 256>>>(
        nh, H_ENC, W_att + H_ENC, 2 * H_ENC, b_att, pP, H_ENC, H_ENC);
    k_init_state<<<256, 256>>>(nh, root, labels);
    k_zero_out0<<<512, 256>>>(out);

    // ---- decode steps ----
    for (int t = 1; t < LSEQ; t++) {
        float* slab = out + (size_t)t * BV;
        k_step_init<<<1024, 256>>>(emb);
        // Qh = h @ W_att[:,:512]^T   (split-K 8)
        sgemm_kernel<true><<<dim3(1, H_ENC / BN, 8), 256>>>(
            pH, H_ENC, W_att, 2 * H_ENC, nullptr, pQh, H_ENC, H_ENC / 8);
        k_attention<<<BATCH, 256>>>(nh, root, v_att);
        // gates = x @ [W_ih|W_hh]^T + (b_ih+b_hh)   (split-K 8)
        sgemm_kernel<true><<<dim3(1, G4 / BN, 8), 256>>>(
            pX, KX, pWg, KX, pBg, pGates, G4, KX / 8);
        k_lstm<<<512, 256>>>(slab);
        // logits = h @ W_out^T + b_out   (split-K 4, written into d_out slab)
        sgemm_kernel<true><<<dim3(1, VOCAB / BN, 4), 256>>>(
            pH, H_ENC, W_out, H_ENC, b_out, slab, VOCAB, H_ENC / 4);
        k_argmax<<<BATCH, 256>>>(slab);
    }
}

// round 3
// speedup vs baseline: 1.0446x; 1.0446x over previous
#include <cuda_runtime.h>

#define H_ENC 512
#define H_DEC 256
#define VOCAB 8192
#define BATCH 128
#define NTOT  16384
#define LSEQ  13
#define KX    1280           // H_DEC + H_ENC (attended) + H_ENC (h)
#define G4    2048           // 4*H_ENC
#define BV    (BATCH*VOCAB)  // 1048576

#define QH_SPLITS 8
#define GT_SPLITS 8
#define LG_SPLITS 4

// ---------------- device scratch (no cudaMalloc allowed) ----------------
__device__ float g_P[NTOT * H_ENC];                 // 32 MB: nh @ W_att2^T + b_att
__device__ float g_h[BATCH * H_ENC];
__device__ float g_c[BATCH * H_ENC];
__device__ float g_x[BATCH * KX];                   // [emb | attended | h]
__device__ float g_score[NTOT];
__device__ float g_Wg[G4 * KX];                     // [W_ih | W_hh] along K
__device__ float g_bg[G4];                          // b_ih + b_hh
__device__ float g_QhP[QH_SPLITS * BATCH * H_ENC];  // split-K partials
__device__ float g_gatesP[GT_SPLITS * BATCH * G4];
__device__ float g_logitsP[LG_SPLITS * BV];

// ---------------- helpers ----------------
__device__ __forceinline__ unsigned long long pack2(float a) {
    unsigned long long r;
    asm("mov.b64 %0, {%1, %1};" : "=l"(r) : "f"(a));
    return r;
}
__device__ __forceinline__ void ffma2(unsigned long long& d, unsigned long long a,
                                      unsigned long long b) {
    asm("fma.rn.f32x2 %0, %1, %2, %0;" : "+l"(d) : "l"(a), "l"(b));
}
__device__ __forceinline__ float fast_tanh(float x) {
    float e = __expf(2.0f * x);
    float r;
    asm("rcp.approx.f32 %0, %1;" : "=f"(r) : "f"(e + 1.0f));
    return 1.0f - 2.0f * r;
}
__device__ __forceinline__ float fsigm(float x) {
    float e = __expf(-x);
    float r;
    asm("rcp.approx.f32 %0, %1;" : "=f"(r) : "f"(e + 1.0f));
    return r;
}

// ---------------- SGEMM: C[M,N] = A[M,K] @ W[N,K]^T (+bias if !SPLIT) ----------------
// grid (M/128, N/64, splits). SPLIT: each z writes its own partial buffer (no atomics).
// Register-prefetch double buffering hides global latency across the compute phase.
#define BM  128
#define BN  64
#define BKK 16

template<bool SPLIT>
__global__ void __launch_bounds__(256) sgemm_kernel(
    const float* __restrict__ A, int lda,
    const float* __restrict__ W, int ldw,
    const float* __restrict__ bias,
    float* __restrict__ C, int ldc,
    int kPerSplit, int strideZ)
{
    __shared__ float As[BKK][132];   // [k][m], padded
    __shared__ float Ws[BKK][68];    // [k][n], padded

    const int tid = threadIdx.x;
    const int rowBase = blockIdx.x * BM;
    const int colBase = blockIdx.y * BN;
    const int kBase0  = blockIdx.z * kPerSplit;
    if (SPLIT) C += (size_t)blockIdx.z * strideZ;

    const int tr = tid >> 3;   // 0..31 -> 4 rows each
    const int tc = tid & 7;    // 0..7  -> 8 cols each

    unsigned long long acc[4][4];
#pragma unroll
    for (int i = 0; i < 4; i++)
#pragma unroll
        for (int j = 0; j < 4; j++) acc[i][j] = 0ull;

    const int aRow = tid >> 2;          // 0..63
    const int wRow = tid >> 2;          // 0..63
    const int kq   = (tid & 3) * 4;
    const int nIters = kPerSplit / BKK;

    float4 pa0, pa1, pw;
    // prime: load tile 0
    {
        const int kb = kBase0;
        pa0 = *(const float4*)(A + (size_t)(rowBase + aRow) * lda + kb + kq);
        pa1 = *(const float4*)(A + (size_t)(rowBase + aRow + 64) * lda + kb + kq);
        pw  = *(const float4*)(W + (size_t)(colBase + wRow) * ldw + kb + kq);
    }
    As[kq + 0][aRow] = pa0.x; As[kq + 1][aRow] = pa0.y;
    As[kq + 2][aRow] = pa0.z; As[kq + 3][aRow] = pa0.w;
    As[kq + 0][aRow + 64] = pa1.x; As[kq + 1][aRow + 64] = pa1.y;
    As[kq + 2][aRow + 64] = pa1.z; As[kq + 3][aRow + 64] = pa1.w;
    Ws[kq + 0][wRow] = pw.x; Ws[kq + 1][wRow] = pw.y;
    Ws[kq + 2][wRow] = pw.z; Ws[kq + 3][wRow] = pw.w;
    __syncthreads();

    for (int ko = 0; ko < nIters; ++ko) {
        const bool more = (ko + 1 < nIters);
        if (more) {
            const int kb = kBase0 + (ko + 1) * BKK;
            pa0 = *(const float4*)(A + (size_t)(rowBase + aRow) * lda + kb + kq);
            pa1 = *(const float4*)(A + (size_t)(rowBase + aRow + 64) * lda + kb + kq);
            pw  = *(const float4*)(W + (size_t)(colBase + wRow) * ldw + kb + kq);
        }
#pragma unroll
        for (int k = 0; k < BKK; k++) {
            float4 av = *(const float4*)&As[k][tr * 4];
            ulonglong2 b0 = *(const ulonglong2*)&Ws[k][tc * 8];
            ulonglong2 b1 = *(const ulonglong2*)&Ws[k][tc * 8 + 4];
            unsigned long long a0 = pack2(av.x), a1 = pack2(av.y);
            unsigned long long a2 = pack2(av.z), a3 = pack2(av.w);
            ffma2(acc[0][0], a0, b0.x); ffma2(acc[0][1], a0, b0.y);
            ffma2(acc[0][2], a0, b1.x); ffma2(acc[0][3], a0, b1.y);
            ffma2(acc[1][0], a1, b0.x); ffma2(acc[1][1], a1, b0.y);
            ffma2(acc[1][2], a1, b1.x); ffma2(acc[1][3], a1, b1.y);
            ffma2(acc[2][0], a2, b0.x); ffma2(acc[2][1], a2, b0.y);
            ffma2(acc[2][2], a2, b1.x); ffma2(acc[2][3], a2, b1.y);
            ffma2(acc[3][0], a3, b0.x); ffma2(acc[3][1], a3, b0.y);
            ffma2(acc[3][2], a3, b1.x); ffma2(acc[3][3], a3, b1.y);
        }
        __syncthreads();
        if (more) {
            As[kq + 0][aRow] = pa0.x; As[kq + 1][aRow] = pa0.y;
            As[kq + 2][aRow] = pa0.z; As[kq + 3][aRow] = pa0.w;
            As[kq + 0][aRow + 64] = pa1.x; As[kq + 1][aRow + 64] = pa1.y;
            As[kq + 2][aRow + 64] = pa1.z; As[kq + 3][aRow + 64] = pa1.w;
            Ws[kq + 0][wRow] = pw.x; Ws[kq + 1][wRow] = pw.y;
            Ws[kq + 2][wRow] = pw.z; Ws[kq + 3][wRow] = pw.w;
            __syncthreads();
        }
    }

    const int row0 = rowBase + tr * 4;
    const int col0 = colBase + tc * 8;
#pragma unroll
    for (int i = 0; i < 4; i++) {
#pragma unroll
        for (int j = 0; j < 4; j++) {
            union { unsigned long long u; float2 f; } v;
            v.u = acc[i][j];
            const int col = col0 + j * 2;
            if (!SPLIT && bias != nullptr) {
                v.f.x += bias[col];
                v.f.y += bias[col + 1];
            }
            *(float2*)(C + (size_t)(row0 + i) * ldc + col) = v.f;
        }
    }
}

// ---------------- setup kernels ----------------
__global__ void __launch_bounds__(256) k_concatW(
    const float* __restrict__ W_ih, const float* __restrict__ W_hh,
    const float* __restrict__ b_ih, const float* __restrict__ b_hh)
{
    const int total = G4 * KX;
    for (int idx = blockIdx.x * blockDim.x + threadIdx.x; idx < total;
         idx += gridDim.x * blockDim.x) {
        int j = idx / KX;
        int k = idx - j * KX;
        g_Wg[idx] = (k < H_DEC + H_ENC) ? W_ih[j * (H_DEC + H_ENC) + k]
                                        : W_hh[j * H_ENC + (k - H_DEC - H_ENC)];
    }
    int gid = blockIdx.x * blockDim.x + threadIdx.x;
    if (gid < G4) g_bg[gid] = b_ih[gid] + b_hh[gid];
}

__global__ void __launch_bounds__(256) k_init_state(
    const float* __restrict__ nh, const int* __restrict__ root,
    const int* __restrict__ labels, const float* __restrict__ emb)
{
    int idx = blockIdx.x * blockDim.x + threadIdx.x;   // 65536
    int b = idx >> 9, j = idx & 511;
    float h0 = nh[(size_t)root[b] * H_ENC + j];
    g_h[idx] = h0;
    g_c[idx] = 0.0f;
    g_x[b * KX + H_DEC + H_ENC + j] = h0;              // h slot
    if (idx < BATCH * H_DEC) {
        int be = idx >> 8, je = idx & 255;
        g_x[be * KX + je] = emb[(size_t)labels[be] * H_DEC + je];  // emb from labels[0]
    }
}

__global__ void __launch_bounds__(256) k_zero_out0(float* __restrict__ out) {
    for (int i = blockIdx.x * blockDim.x + threadIdx.x; i < BV;
         i += gridDim.x * blockDim.x)
        out[i] = 0.0f;
}

// ---------------- per-step kernels ----------------
// fused: Qh partial-reduce -> score -> segment softmax -> attended; 1 block / segment
__global__ void __launch_bounds__(256) k_attention(
    const float* __restrict__ nh, const int* __restrict__ root,
    const float* __restrict__ v_att)
{
    const int b = blockIdx.x;
    const int tid = threadIdx.x, lid = tid & 31, wid = tid >> 5;
    __shared__ float sQ[H_ENC], sV[H_ENC];
    __shared__ float sred[8];
    __shared__ float s_m, s_invz;
    __shared__ float wbuf[256];

    const int s0 = root[b];
    const int s1 = (b == BATCH - 1) ? NTOT : root[b + 1];

    for (int j = tid; j < H_ENC; j += 256) {
        float q = 0.0f;
#pragma unroll
        for (int z = 0; z < QH_SPLITS; z++)
            q += g_QhP[z * (BATCH * H_ENC) + b * H_ENC + j];
        sQ[j] = q;
        sV[j] = v_att[j];
    }
    __syncthreads();

    // pass 1: score[n] = sum_j v[j] * tanh(P[n,j] + Qh[b,j])   (b_att folded into P)
    const float2* sQ2 = (const float2*)sQ;
    const float2* sV2 = (const float2*)sV;
    for (int n = s0 + wid; n < s1; n += 8) {
        const float2* Pr2 = (const float2*)(g_P + (size_t)n * H_ENC);
        float acc = 0.0f;
#pragma unroll
        for (int it = 0; it < 8; ++it) {
            int j = lid + it * 32;
            float2 p = Pr2[j], q = sQ2[j], vv = sV2[j];
            acc += vv.x * fast_tanh(p.x + q.x) + vv.y * fast_tanh(p.y + q.y);
        }
#pragma unroll
        for (int o = 16; o; o >>= 1) acc += __shfl_xor_sync(0xffffffffu, acc, o);
        if (lid == 0) g_score[n] = acc;
    }
    __syncthreads();

    // pass 2: segment max
    float m = -3.402823466e38f;
    for (int n = s0 + tid; n < s1; n += 256) m = fmaxf(m, g_score[n]);
#pragma unroll
    for (int o = 16; o; o >>= 1) m = fmaxf(m, __shfl_xor_sync(0xffffffffu, m, o));
    if (lid == 0) sred[wid] = m;
    __syncthreads();
    if (tid == 0) {
        float mm = sred[0];
        for (int w = 1; w < 8; w++) mm = fmaxf(mm, sred[w]);
        s_m = mm;
    }
    __syncthreads();
    m = s_m;

    // pass 3: segment sum of exp
    float z = 0.0f;
    for (int n = s0 + tid; n < s1; n += 256) z += __expf(g_score[n] - m);
#pragma unroll
    for (int o = 16; o; o >>= 1) z += __shfl_xor_sync(0xffffffffu, z, o);
    if (lid == 0) sred[wid] = z;
    __syncthreads();
    if (tid == 0) {
        float zz = 0.0f;
        for (int w = 0; w < 8; w++) zz += sred[w];
        s_invz = 1.0f / zz;
    }
    __syncthreads();
    const float invz = s_invz;

    // pass 4: attended[b, :] = sum_n w_n * nh[n, :]
    float2 a = make_float2(0.0f, 0.0f);
    for (int cs = s0; cs < s1; cs += 256) {
        const int cn = min(256, s1 - cs);
        __syncthreads();
        if (tid < cn) wbuf[tid] = __expf(g_score[cs + tid] - m);
        __syncthreads();
#pragma unroll 4
        for (int i = 0; i < cn; i++) {
            float w = wbuf[i];
            float2 r = *(const float2*)(nh + (size_t)(cs + i) * H_ENC + 2 * tid);
            a.x += w * r.x;
            a.y += w * r.y;
        }
    }
    a.x *= invz; a.y *= invz;
    *(float2*)&g_x[b * KX + H_DEC + 2 * tid] = a;
}

// fused: gate partial-reduce + bias + LSTM update; writes h, c, and h slot of x
__global__ void __launch_bounds__(256) k_lstm() {
    const int idx = blockIdx.x * blockDim.x + threadIdx.x;   // 65536
    const int b = idx >> 9, j = idx & 511;
    float ig = g_bg[j], fg = g_bg[512 + j], gg = g_bg[1024 + j], og = g_bg[1536 + j];
#pragma unroll
    for (int z = 0; z < GT_SPLITS; z++) {
        const float* gr = g_gatesP + (size_t)z * (BATCH * G4) + b * G4 + j;
        ig += gr[0]; fg += gr[512]; gg += gr[1024]; og += gr[1536];
    }
    float c = fsigm(fg) * g_c[idx] + fsigm(ig) * fast_tanh(gg);
    g_c[idx] = c;
    float h = fsigm(og) * fast_tanh(c);
    g_h[idx] = h;
    g_x[b * KX + H_DEC + H_ENC + j] = h;
}

// fused: logits partial-reduce + bias + store slab + argmax + gather next emb
__global__ void __launch_bounds__(256) k_out(
    const float* __restrict__ b_out, const float* __restrict__ emb,
    float* __restrict__ slab)
{
    const int b = blockIdx.x, tid = threadIdx.x;
    float* row = slab + (size_t)b * VOCAB;
    float best = -3.402823466e38f;
    int bi = VOCAB;
    for (int j = tid; j < VOCAB; j += 256) {
        float v = b_out[j];
#pragma unroll
        for (int z = 0; z < LG_SPLITS; z++)
            v += g_logitsP[(size_t)z * BV + (size_t)b * VOCAB + j];
        row[j] = v;
        if (v > best) { best = v; bi = j; }   // ascending j keeps first max per thread
    }
    __shared__ float sv[256];
    __shared__ int si[256];
    __shared__ int s_cur;
    sv[tid] = best; si[tid] = bi;
    __syncthreads();
    for (int s = 128; s; s >>= 1) {
        if (tid < s) {
            float v2 = sv[tid + s]; int i2 = si[tid + s];
            if (v2 > sv[tid] || (v2 == sv[tid] && i2 < si[tid])) { sv[tid] = v2; si[tid] = i2; }
        }
        __syncthreads();
    }
    if (tid == 0) s_cur = si[0];
    __syncthreads();
    // emb slot for next step: H_DEC == 256 == blockDim
    g_x[b * KX + tid] = emb[(size_t)s_cur * H_DEC + tid];
}

// ---------------- launch ----------------
extern "C" void kernel_launch(void* const* d_in, const int* in_sizes, int n_in,
                              void* d_out, int out_size) {
    const float* nh    = (const float*)d_in[0];
    const int*   labels= (const int*)  d_in[1];
    const int*   root  = (const int*)  d_in[2];
    const float* emb   = (const float*)d_in[3];
    const float* W_att = (const float*)d_in[4];
    const float* b_att = (const float*)d_in[5];
    const float* v_att = (const float*)d_in[6];
    const float* W_ih  = (const float*)d_in[7];
    const float* W_hh  = (const float*)d_in[8];
    const float* b_ih  = (const float*)d_in[9];
    const float* b_hh  = (const float*)d_in[10];
    const float* W_out = (const float*)d_in[11];
    const float* b_out = (const float*)d_in[12];
    float* out = (float*)d_out;

    float *pP, *pH, *pX, *pWg, *pQhP, *pGatesP, *pLogitsP;
    cudaGetSymbolAddress((void**)&pP, g_P);
    cudaGetSymbolAddress((void**)&pH, g_h);
    cudaGetSymbolAddress((void**)&pX, g_x);
    cudaGetSymbolAddress((void**)&pWg, g_Wg);
    cudaGetSymbolAddress((void**)&pQhP, g_QhP);
    cudaGetSymbolAddress((void**)&pGatesP, g_gatesP);
    cudaGetSymbolAddress((void**)&pLogitsP, g_logitsP);

    // ---- setup ----
    k_concatW<<<1280, 256>>>(W_ih, W_hh, b_ih, b_hh);
    // P = nh @ W_att[:,512:]^T + b_att   (step-invariant)
    sgemm_kernel<false><<<dim3(NTOT / BM, H_ENC / BN, 1), 256>>>(
        nh, H_ENC, W_att + H_ENC, 2 * H_ENC, b_att, pP, H_ENC, H_ENC, 0);
    k_init_state<<<256, 256>>>(nh, root, labels, emb);
    k_zero_out0<<<512, 256>>>(out);

    // ---- decode steps ----
    for (int t = 1; t < LSEQ; t++) {
        float* slab = out + (size_t)t * BV;
        // Qh partials = h @ W_att[:,:512]^T
        sgemm_kernel<true><<<dim3(1, H_ENC / BN, QH_SPLITS), 256>>>(
            pH, H_ENC, W_att, 2 * H_ENC, nullptr, pQhP, H_ENC,
            H_ENC / QH_SPLITS, BATCH * H_ENC);
        k_attention<<<BATCH, 256>>>(nh, root, v_att);
        // gates partials = x @ [W_ih|W_hh]^T
        sgemm_kernel<true><<<dim3(1, G4 / BN, GT_SPLITS), 256>>>(
            pX, KX, pWg, KX, nullptr, pGatesP, G4,
            KX / GT_SPLITS, BATCH * G4);
        k_lstm<<<256, 256>>>();
        // logits partials = h @ W_out^T
        sgemm_kernel<true><<<dim3(1, VOCAB / BN, LG_SPLITS), 256>>>(
            pH, H_ENC, W_out, H_ENC, nullptr, pLogitsP, VOCAB,
            H_ENC / LG_SPLITS, BV);
        k_out<<<BATCH, 256>>>(b_out, emb, slab);
    }
}

// round 5
// speedup vs baseline: 1.4309x; 1.3698x over previous
#include <cuda_runtime.h>
#include <cuda_bf16.h>
#include <cstdint>

#define H_ENC 512
#define H_DEC 256
#define VOCAB 8192
#define BATCH 128
#define NTOT  16384
#define LSEQ  13
#define KX    1280           // H_DEC + H_ENC (attended) + H_ENC (h)
#define G4    2048           // 4*H_ENC
#define BV    (BATCH*VOCAB)  // 1048576

#define KP_H  1536           // 3*512  (split-K' for K=512 operands)
#define KP_X  3840           // 3*1280 (split-K' for x)

#define QH_SPLITS 8
#define GT_SPLITS 10
#define LG_SPLITS 4

// ---------------- device scratch (no cudaMalloc allowed) ----------------
__device__ float g_P[NTOT * H_ENC];                 // 32 MB fp32: nh @ W_att2^T + b_att
__device__ float g_c[BATCH * H_ENC];
__device__ float g_score[NTOT];
__device__ float g_bg[G4];                          // b_ih + b_hh
__device__ float g_QhP[QH_SPLITS * BATCH * H_ENC];  // split-K partials (fp32)
__device__ float g_gatesP[GT_SPLITS * BATCH * G4];
__device__ float g_logitsP[LG_SPLITS * BV];
// split-bf16 interleaved operands: [hi | hi | lo] along K'
__device__ __nv_bfloat16 g_hb [BATCH * KP_H];       // h
__device__ __nv_bfloat16 g_xb [BATCH * KP_X];       // x = [emb | attended | h]
__device__ __nv_bfloat16 g_nhb[NTOT * KP_H];        // node_hidden_states
// split-bf16 interleaved weights: [hi | lo | hi] along K'
__device__ __nv_bfloat16 g_Wab1[H_ENC * KP_H];      // W_att[:, :512]  (Qh)
__device__ __nv_bfloat16 g_Wab2[H_ENC * KP_H];      // W_att[:, 512:]  (P)
__device__ __nv_bfloat16 g_Wgb [G4 * KP_X];         // [W_ih | W_hh]
__device__ __nv_bfloat16 g_Wob [VOCAB * KP_H];      // W_out

// ---------------- math helpers ----------------
__device__ __forceinline__ float fast_tanh(float x) {
    float e = __expf(2.0f * x), r;
    asm("rcp.approx.f32 %0, %1;" : "=f"(r) : "f"(e + 1.0f));
    return 1.0f - 2.0f * r;
}
__device__ __forceinline__ float fsigm(float x) {
    float e = __expf(-x), r;
    asm("rcp.approx.f32 %0, %1;" : "=f"(r) : "f"(e + 1.0f));
    return r;
}
__device__ __forceinline__ void split2(float v, __nv_bfloat16& hi, __nv_bfloat16& lo) {
    hi = __float2bfloat16(v);
    lo = __float2bfloat16(v - __bfloat162float(hi));
}

__device__ __forceinline__ void mma16816(float* d, const uint32_t* a, const uint32_t* b) {
    asm volatile(
        "mma.sync.aligned.m16n8k16.row.col.f32.bf16.bf16.f32 "
        "{%0,%1,%2,%3}, {%4,%5,%6,%7}, {%8,%9}, {%0,%1,%2,%3};"
        : "+f"(d[0]), "+f"(d[1]), "+f"(d[2]), "+f"(d[3])
        : "r"(a[0]), "r"(a[1]), "r"(a[2]), "r"(a[3]), "r"(b[0]), "r"(b[1]));
}

// ---------------- HMMA GEMM: C[M,N] = A'[M,K'] @ W'[N,K']^T (bf16->fp32) ------
// grid (M/128, N/64, splits); block 256 = 8 warps (4 M x 2 N), warp tile 32x32.
// K chunked by 64. SPLIT: z writes its own partial buffer. bias added if !SPLIT.
template<bool SPLIT>
__global__ void __launch_bounds__(256, 2) mma_gemm(
    const __nv_bfloat16* __restrict__ A, int lda,
    const __nv_bfloat16* __restrict__ W, int ldw,
    const float* __restrict__ bias,
    float* __restrict__ C, int ldc,
    int chunks, int strideZ)
{
    __shared__ __nv_bfloat16 As[128][72];   // 64 data + 8 pad
    __shared__ __nv_bfloat16 Ws[64][72];

    const int tid = threadIdx.x;
    const int wid = tid >> 5, lane = tid & 31;
    const int wm = wid & 3;          // M warp index: rows wm*32
    const int wn = wid >> 2;         // N warp index: cols wn*32
    const int g = lane >> 2, tid4 = lane & 3;

    const int rowBase = blockIdx.x * 128, colBase = blockIdx.y * 64;
    const long kBase = (long)blockIdx.z * chunks * 64;
    if (SPLIT) C += (size_t)blockIdx.z * strideZ;

    float acc[2][4][4];
#pragma unroll
    for (int i = 0; i < 2; i++)
#pragma unroll
        for (int j = 0; j < 4; j++)
#pragma unroll
            for (int v = 0; v < 4; v++) acc[i][j][v] = 0.0f;

    // gmem load assignments
    const int aRow = tid >> 1, aSeg = (tid & 1) * 32;              // 4 uint4 per thread
    const __nv_bfloat16* aSrc = A + (size_t)(rowBase + aRow) * lda + aSeg;

    uint4 pa[4], pb[2];
    // prime chunk 0
    {
        const long k0 = kBase;
#pragma unroll
        for (int i = 0; i < 4; i++)
            pa[i] = *(const uint4*)(aSrc + k0 + i * 8);
#pragma unroll
        for (int i = 0; i < 2; i++) {
            int u = tid + i * 256, row = u >> 3, seg = u & 7;
            pb[i] = *(const uint4*)(W + (size_t)(colBase + row) * ldw + k0 + seg * 8);
        }
    }

    for (int c = 0; c < chunks; ++c) {
        // store staged regs to smem
#pragma unroll
        for (int i = 0; i < 4; i++)
            *(uint4*)&As[aRow][aSeg + i * 8] = pa[i];
#pragma unroll
        for (int i = 0; i < 2; i++) {
            int u = tid + i * 256, row = u >> 3, seg = u & 7;
            *(uint4*)&Ws[row][seg * 8] = pb[i];
        }
        __syncthreads();

        // prefetch next chunk
        if (c + 1 < chunks) {
            const long k0 = kBase + (long)(c + 1) * 64;
#pragma unroll
            for (int i = 0; i < 4; i++)
                pa[i] = *(const uint4*)(aSrc + k0 + i * 8);
#pragma unroll
            for (int i = 0; i < 2; i++) {
                int u = tid + i * 256, row = u >> 3, seg = u & 7;
                pb[i] = *(const uint4*)(W + (size_t)(colBase + row) * ldw + k0 + seg * 8);
            }
        }

        // compute: 4 k-steps of 16
#pragma unroll
        for (int ks = 0; ks < 4; ks++) {
            const int kk = ks * 16;
            uint32_t af[2][4];
#pragma unroll
            for (int i = 0; i < 2; i++) {
                const int r = wm * 32 + i * 16 + g;
                af[i][0] = *(const uint32_t*)&As[r][kk + 2 * tid4];
                af[i][1] = *(const uint32_t*)&As[r + 8][kk + 2 * tid4];
                af[i][2] = *(const uint32_t*)&As[r][kk + 2 * tid4 + 8];
                af[i][3] = *(const uint32_t*)&As[r + 8][kk + 2 * tid4 + 8];
            }
            uint32_t bfr[4][2];
#pragma unroll
            for (int j = 0; j < 4; j++) {
                const int n = wn * 32 + j * 8 + g;
                bfr[j][0] = *(const uint32_t*)&Ws[n][kk + 2 * tid4];
                bfr[j][1] = *(const uint32_t*)&Ws[n][kk + 2 * tid4 + 8];
            }
#pragma unroll
            for (int i = 0; i < 2; i++)
#pragma unroll
                for (int j = 0; j < 4; j++)
                    mma16816(acc[i][j], af[i], bfr[j]);
        }
        __syncthreads();
    }

    // epilogue
    const int row0 = rowBase + wm * 32;
    const int col0 = colBase + wn * 32;
#pragma unroll
    for (int i = 0; i < 2; i++) {
#pragma unroll
        for (int j = 0; j < 4; j++) {
            const int r0 = row0 + i * 16 + g;
            const int cc = col0 + j * 8 + 2 * tid4;
            float2 v0 = make_float2(acc[i][j][0], acc[i][j][1]);
            float2 v1 = make_float2(acc[i][j][2], acc[i][j][3]);
            if (!SPLIT) {
                float2 bb = *(const float2*)(bias + cc);
                v0.x += bb.x; v0.y += bb.y;
                v1.x += bb.x; v1.y += bb.y;
            }
            *(float2*)(C + (size_t)r0 * ldc + cc) = v0;
            *(float2*)(C + (size_t)(r0 + 8) * ldc + cc) = v1;
        }
    }
}

// ---------------- setup: convert all weights + nh to split-bf16 ----------------
#define S0 (H_ENC * H_ENC)     // W_att halves (handled together)
#define S1 (G4 * KX)           // Wg
#define S2 (VOCAB * H_ENC)     // W_out
#define S3 (NTOT * H_ENC)      // nh
__global__ void __launch_bounds__(256) k_convert(
    const float* __restrict__ W_att, const float* __restrict__ W_ih,
    const float* __restrict__ W_hh, const float* __restrict__ W_out,
    const float* __restrict__ nh,
    const float* __restrict__ b_ih, const float* __restrict__ b_hh)
{
    const int total = S0 + S1 + S2 + S3;
    int gid = blockIdx.x * blockDim.x + threadIdx.x;
    if (gid < G4) g_bg[gid] = b_ih[gid] + b_hh[gid];
    for (int idx = gid; idx < total; idx += gridDim.x * blockDim.x) {
        if (idx < S0) {
            int n = idx >> 9, k = idx & 511;
            __nv_bfloat16 hi, lo;
            split2(W_att[n * 1024 + k], hi, lo);
            g_Wab1[n * KP_H + k] = hi; g_Wab1[n * KP_H + 512 + k] = lo;
            g_Wab1[n * KP_H + 1024 + k] = hi;
            split2(W_att[n * 1024 + 512 + k], hi, lo);
            g_Wab2[n * KP_H + k] = hi; g_Wab2[n * KP_H + 512 + k] = lo;
            g_Wab2[n * KP_H + 1024 + k] = hi;
        } else if (idx < S0 + S1) {
            int t = idx - S0;
            int n = t / KX, k = t - n * KX;
            float v = (k < 768) ? W_ih[n * 768 + k] : W_hh[n * 512 + (k - 768)];
            __nv_bfloat16 hi, lo;
            split2(v, hi, lo);
            g_Wgb[(size_t)n * KP_X + k] = hi;
            g_Wgb[(size_t)n * KP_X + 1280 + k] = lo;
            g_Wgb[(size_t)n * KP_X + 2560 + k] = hi;
        } else if (idx < S0 + S1 + S2) {
            int t = idx - S0 - S1;
            int n = t >> 9, k = t & 511;
            __nv_bfloat16 hi, lo;
            split2(W_out[(size_t)n * 512 + k], hi, lo);
            g_Wob[(size_t)n * KP_H + k] = hi;
            g_Wob[(size_t)n * KP_H + 512 + k] = lo;
            g_Wob[(size_t)n * KP_H + 1024 + k] = hi;
        } else {
            int t = idx - S0 - S1 - S2;
            int n = t >> 9, k = t & 511;
            __nv_bfloat16 hi, lo;
            split2(nh[(size_t)n * 512 + k], hi, lo);
            g_nhb[(size_t)n * KP_H + k] = hi;        // A layout: [hi | hi | lo]
            g_nhb[(size_t)n * KP_H + 512 + k] = hi;
            g_nhb[(size_t)n * KP_H + 1024 + k] = lo;
        }
    }
}

__global__ void __launch_bounds__(256) k_init_state(
    const float* __restrict__ nh, const int* __restrict__ root,
    const int* __restrict__ labels, const float* __restrict__ emb)
{
    int idx = blockIdx.x * blockDim.x + threadIdx.x;   // 65536
    int b = idx >> 9, j = idx & 511;
    float h0 = nh[(size_t)root[b] * H_ENC + j];
    g_c[idx] = 0.0f;
    __nv_bfloat16 hi, lo;
    split2(h0, hi, lo);
    g_hb[b * KP_H + j] = hi; g_hb[b * KP_H + 512 + j] = hi; g_hb[b * KP_H + 1024 + j] = lo;
    g_xb[b * KP_X + 768 + j] = hi; g_xb[b * KP_X + 2048 + j] = hi; g_xb[b * KP_X + 3328 + j] = lo;
    if (idx < BATCH * H_DEC) {
        int be = idx >> 8, je = idx & 255;
        float e = emb[(size_t)labels[be] * H_DEC + je];
        split2(e, hi, lo);
        g_xb[be * KP_X + je] = hi; g_xb[be * KP_X + 1280 + je] = hi; g_xb[be * KP_X + 2560 + je] = lo;
    }
}

__global__ void __launch_bounds__(256) k_zero_out0(float* __restrict__ out) {
    for (int i = blockIdx.x * blockDim.x + threadIdx.x; i < BV;
         i += gridDim.x * blockDim.x)
        out[i] = 0.0f;
}

// ---------------- per-step kernels ----------------
__global__ void __launch_bounds__(256) k_attention(
    const float* __restrict__ nh, const int* __restrict__ root,
    const float* __restrict__ v_att)
{
    const int b = blockIdx.x;
    const int tid = threadIdx.x, lid = tid & 31, wid = tid >> 5;
    __shared__ float sQ[H_ENC], sV[H_ENC];
    __shared__ float sred[8];
    __shared__ float s_m, s_invz;
    __shared__ float wbuf[256];

    const int s0 = root[b];
    const int s1 = (b == BATCH - 1) ? NTOT : root[b + 1];

    for (int j = tid; j < H_ENC; j += 256) {
        float q = 0.0f;
#pragma unroll
        for (int z = 0; z < QH_SPLITS; z++)
            q += g_QhP[z * (BATCH * H_ENC) + b * H_ENC + j];
        sQ[j] = q;
        sV[j] = v_att[j];
    }
    __syncthreads();

    const float2* sQ2 = (const float2*)sQ;
    const float2* sV2 = (const float2*)sV;
    for (int n = s0 + wid; n < s1; n += 8) {
        const float2* Pr2 = (const float2*)(g_P + (size_t)n * H_ENC);
        float acc = 0.0f;
#pragma unroll
        for (int it = 0; it < 8; ++it) {
            int j = lid + it * 32;
            float2 p = Pr2[j], q = sQ2[j], vv = sV2[j];
            acc += vv.x * fast_tanh(p.x + q.x) + vv.y * fast_tanh(p.y + q.y);
        }
#pragma unroll
        for (int o = 16; o; o >>= 1) acc += __shfl_xor_sync(0xffffffffu, acc, o);
        if (lid == 0) g_score[n] = acc;
    }
    __syncthreads();

    float m = -3.402823466e38f;
    for (int n = s0 + tid; n < s1; n += 256) m = fmaxf(m, g_score[n]);
#pragma unroll
    for (int o = 16; o; o >>= 1) m = fmaxf(m, __shfl_xor_sync(0xffffffffu, m, o));
    if (lid == 0) sred[wid] = m;
    __syncthreads();
    if (tid == 0) {
        float mm = sred[0];
        for (int w = 1; w < 8; w++) mm = fmaxf(mm, sred[w]);
        s_m = mm;
    }
    __syncthreads();
    m = s_m;

    float z = 0.0f;
    for (int n = s0 + tid; n < s1; n += 256) z += __expf(g_score[n] - m);
#pragma unroll
    for (int o = 16; o; o >>= 1) z += __shfl_xor_sync(0xffffffffu, z, o);
    if (lid == 0) sred[wid] = z;
    __syncthreads();
    if (tid == 0) {
        float zz = 0.0f;
        for (int w = 0; w < 8; w++) zz += sred[w];
        s_invz = 1.0f / zz;
    }
    __syncthreads();
    const float invz = s_invz;

    float2 a = make_float2(0.0f, 0.0f);
    for (int cs = s0; cs < s1; cs += 256) {
        const int cn = min(256, s1 - cs);
        __syncthreads();
        if (tid < cn) wbuf[tid] = __expf(g_score[cs + tid] - m);
        __syncthreads();
#pragma unroll 4
        for (int i = 0; i < cn; i++) {
            float w = wbuf[i];
            float2 r = *(const float2*)(nh + (size_t)(cs + i) * H_ENC + 2 * tid);
            a.x += w * r.x;
            a.y += w * r.y;
        }
    }
    a.x *= invz; a.y *= invz;
    // write attended (cols 256..768 of x) in split-bf16
    const int c0 = 2 * tid;
    __nv_bfloat16 hi, lo;
    split2(a.x, hi, lo);
    g_xb[b * KP_X + 256 + c0] = hi; g_xb[b * KP_X + 1536 + c0] = hi; g_xb[b * KP_X + 2816 + c0] = lo;
    split2(a.y, hi, lo);
    g_xb[b * KP_X + 257 + c0] = hi; g_xb[b * KP_X + 1537 + c0] = hi; g_xb[b * KP_X + 2817 + c0] = lo;
}

__global__ void __launch_bounds__(256) k_lstm() {
    const int idx = blockIdx.x * blockDim.x + threadIdx.x;   // 65536
    const int b = idx >> 9, j = idx & 511;
    float ig = g_bg[j], fg = g_bg[512 + j], gg = g_bg[1024 + j], og = g_bg[1536 + j];
#pragma unroll
    for (int z = 0; z < GT_SPLITS; z++) {
        const float* gr = g_gatesP + (size_t)z * (BATCH * G4) + b * G4 + j;
        ig += gr[0]; fg += gr[512]; gg += gr[1024]; og += gr[1536];
    }
    float c = fsigm(fg) * g_c[idx] + fsigm(ig) * fast_tanh(gg);
    g_c[idx] = c;
    float h = fsigm(og) * fast_tanh(c);
    __nv_bfloat16 hi, lo;
    split2(h, hi, lo);
    g_hb[b * KP_H + j] = hi; g_hb[b * KP_H + 512 + j] = hi; g_hb[b * KP_H + 1024 + j] = lo;
    g_xb[b * KP_X + 768 + j] = hi; g_xb[b * KP_X + 2048 + j] = hi; g_xb[b * KP_X + 3328 + j] = lo;
}

__global__ void __launch_bounds__(256) k_out(
    const float* __restrict__ b_out, const float* __restrict__ emb,
    float* __restrict__ slab)
{
    const int b = blockIdx.x, tid = threadIdx.x;
    float* row = slab + (size_t)b * VOCAB;
    float best = -3.402823466e38f;
    int bi = VOCAB;
    for (int j = tid; j < VOCAB; j += 256) {
        float v = b_out[j];
#pragma unroll
        for (int z = 0; z < LG_SPLITS; z++)
            v += g_logitsP[(size_t)z * BV + (size_t)b * VOCAB + j];
        row[j] = v;
        if (v > best) { best = v; bi = j; }
    }
    __shared__ float sv[256];
    __shared__ int si[256];
    __shared__ int s_cur;
    sv[tid] = best; si[tid] = bi;
    __syncthreads();
    for (int s = 128; s; s >>= 1) {
        if (tid < s) {
            float v2 = sv[tid + s]; int i2 = si[tid + s];
            if (v2 > sv[tid] || (v2 == sv[tid] && i2 < si[tid])) { sv[tid] = v2; si[tid] = i2; }
        }
        __syncthreads();
    }
    if (tid == 0) s_cur = si[0];
    __syncthreads();
    float e = emb[(size_t)s_cur * H_DEC + tid];   // H_DEC == 256 == blockDim
    __nv_bfloat16 hi, lo;
    split2(e, hi, lo);
    g_xb[b * KP_X + tid] = hi; g_xb[b * KP_X + 1280 + tid] = hi; g_xb[b * KP_X + 2560 + tid] = lo;
}

// ---------------- launch ----------------
extern "C" void kernel_launch(void* const* d_in, const int* in_sizes, int n_in,
                              void* d_out, int out_size) {
    const float* nh    = (const float*)d_in[0];
    const int*   labels= (const int*)  d_in[1];
    const int*   root  = (const int*)  d_in[2];
    const float* emb   = (const float*)d_in[3];
    const float* W_att = (const float*)d_in[4];
    const float* b_att = (const float*)d_in[5];
    const float* v_att = (const float*)d_in[6];
    const float* W_ih  = (const float*)d_in[7];
    const float* W_hh  = (const float*)d_in[8];
    const float* b_ih  = (const float*)d_in[9];
    const float* b_hh  = (const float*)d_in[10];
    const float* W_out = (const float*)d_in[11];
    const float* b_out = (const float*)d_in[12];
    float* out = (float*)d_out;

    float *pP, *pQhP, *pGatesP, *pLogitsP;
    __nv_bfloat16 *pHb, *pXb, *pNhb, *pWab1, *pWab2, *pWgb, *pWob;
    cudaGetSymbolAddress((void**)&pP, g_P);
    cudaGetSymbolAddress((void**)&pQhP, g_QhP);
    cudaGetSymbolAddress((void**)&pGatesP, g_gatesP);
    cudaGetSymbolAddress((void**)&pLogitsP, g_logitsP);
    cudaGetSymbolAddress((void**)&pHb, g_hb);
    cudaGetSymbolAddress((void**)&pXb, g_xb);
    cudaGetSymbolAddress((void**)&pNhb, g_nhb);
    cudaGetSymbolAddress((void**)&pWab1, g_Wab1);
    cudaGetSymbolAddress((void**)&pWab2, g_Wab2);
    cudaGetSymbolAddress((void**)&pWgb, g_Wgb);
    cudaGetSymbolAddress((void**)&pWob, g_Wob);

    // ---- setup (ordered so the P MMA GEMM is my 4th launch -> ncu lands on it)
    k_convert<<<2048, 256>>>(W_att, W_ih, W_hh, W_out, nh, b_ih, b_hh);
    k_init_state<<<256, 256>>>(nh, root, labels, emb);
    k_zero_out0<<<512, 256>>>(out);
    // P = nh @ W_att[:,512:]^T + b_att   (step-invariant, fp32 out)
    mma_gemm<false><<<dim3(NTOT / 128, H_ENC / 64, 1), 256>>>(
        pNhb, KP_H, pWab2, KP_H, b_att, pP, H_ENC, KP_H / 64, 0);

    // ---- decode steps ----
    for (int t = 1; t < LSEQ; t++) {
        float* slab = out + (size_t)t * BV;
        // Qh partials = h @ W_att[:,:512]^T
        mma_gemm<true><<<dim3(1, H_ENC / 64, QH_SPLITS), 256>>>(
            pHb, KP_H, pWab1, KP_H, nullptr, pQhP, H_ENC,
            KP_H / 64 / QH_SPLITS, BATCH * H_ENC);
        k_attention<<<BATCH, 256>>>(nh, root, v_att);
        // gates partials = x @ [W_ih|W_hh]^T
        mma_gemm<true><<<dim3(1, G4 / 64, GT_SPLITS), 256>>>(
            pXb, KP_X, pWgb, KP_X, nullptr, pGatesP, G4,
            KP_X / 64 / GT_SPLITS, BATCH * G4);
        k_lstm<<<256, 256>>>();
        // logits partials = h @ W_out^T
        mma_gemm<true><<<dim3(1, VOCAB / 64, LG_SPLITS), 256>>>(
            pHb, KP_H, pWob, KP_H, nullptr, pLogitsP, VOCAB,
            KP_H / 64 / LG_SPLITS, BV);
        k_out<<<BATCH, 256>>>(b_out, emb, slab);
    }
}

// round 6
// speedup vs baseline: 1.5560x; 1.0874x over previous
#include <cuda_runtime.h>
#include <cuda_bf16.h>
#include <cstdint>

#define H_ENC 512
#define H_DEC 256
#define VOCAB 8192
#define BATCH 128
#define NTOT  16384
#define LSEQ  13
#define KX    1280           // H_DEC + H_ENC (attended) + H_ENC (h)
#define G4    2048           // 4*H_ENC
#define BV    (BATCH*VOCAB)  // 1048576

#define KP_H  1536           // 3*512  (split-K' for K=512 operands)
#define KP_X  3840           // 3*1280 (split-K' for x)

#define QH_SPLITS 8
#define GT_SPLITS 10
#define LG_SPLITS 4

// ---------------- device scratch (no cudaMalloc allowed) ----------------
__device__ float g_P[NTOT * H_ENC];                 // 32 MB fp32: nh @ W_att2^T + b_att
__device__ float g_c[BATCH * H_ENC];
__device__ float g_score[NTOT];
__device__ float g_bg[G4];                          // b_ih + b_hh
__device__ float g_QhP[QH_SPLITS * BATCH * H_ENC];  // split-K partials (fp32)
__device__ float g_gatesP[GT_SPLITS * BATCH * G4];
__device__ float g_logitsP[LG_SPLITS * BV];
// split-bf16 interleaved operands: [hi | hi | lo] along K'
__device__ __nv_bfloat16 g_hb [BATCH * KP_H];       // h
__device__ __nv_bfloat16 g_xb [BATCH * KP_X];       // x = [emb | attended | h]
__device__ __nv_bfloat16 g_nhb[NTOT * KP_H];        // node_hidden_states
// split-bf16 interleaved weights: [hi | lo | hi] along K'
__device__ __nv_bfloat16 g_Wab1[H_ENC * KP_H];      // W_att[:, :512]  (Qh)
__device__ __nv_bfloat16 g_Wab2[H_ENC * KP_H];      // W_att[:, 512:]  (P)
__device__ __nv_bfloat16 g_Wgb [G4 * KP_X];         // [W_ih | W_hh]
__device__ __nv_bfloat16 g_Wob [VOCAB * KP_H];      // W_out

// ---------------- math helpers ----------------
__device__ __forceinline__ float fast_tanh(float x) {
    float e = __expf(2.0f * x), r;
    asm("rcp.approx.f32 %0, %1;" : "=f"(r) : "f"(e + 1.0f));
    return 1.0f - 2.0f * r;
}
__device__ __forceinline__ float fsigm(float x) {
    float e = __expf(-x), r;
    asm("rcp.approx.f32 %0, %1;" : "=f"(r) : "f"(e + 1.0f));
    return r;
}
__device__ __forceinline__ void split2(float v, __nv_bfloat16& hi, __nv_bfloat16& lo) {
    hi = __float2bfloat16(v);
    lo = __float2bfloat16(v - __bfloat162float(hi));
}
__device__ __forceinline__ uint32_t smem_u32(const void* p) {
    uint32_t a;
    asm("{ .reg .u64 t; cvta.to.shared.u64 t, %1; cvt.u32.u64 %0, t; }"
        : "=r"(a) : "l"(p));
    return a;
}
__device__ __forceinline__ void mma16816(float* d, const uint32_t* a, const uint32_t* b) {
    asm volatile(
        "mma.sync.aligned.m16n8k16.row.col.f32.bf16.bf16.f32 "
        "{%0,%1,%2,%3}, {%4,%5,%6,%7}, {%8,%9}, {%0,%1,%2,%3};"
        : "+f"(d[0]), "+f"(d[1]), "+f"(d[2]), "+f"(d[3])
        : "r"(a[0]), "r"(a[1]), "r"(a[2]), "r"(a[3]), "r"(b[0]), "r"(b[1]));
}
#define LDMX4(r0, r1, r2, r3, addr) \
    asm volatile("ldmatrix.sync.aligned.m8n8.x4.shared.b16 {%0,%1,%2,%3}, [%4];" \
        : "=r"(r0), "=r"(r1), "=r"(r2), "=r"(r3) : "r"(addr))
#define CP16(dst, src) \
    asm volatile("cp.async.cg.shared.global [%0], [%1], 16;" :: "r"(dst), "l"(src))
#define CP_COMMIT() asm volatile("cp.async.commit_group;" ::: "memory")
#define CP_WAIT(n)  asm volatile("cp.async.wait_group %0;" :: "n"(n) : "memory")

// ---------------- HMMA GEMM: C[M,N] = A'[M,K'] @ W'[N,K']^T (bf16->fp32) ------
// grid (M/128, N/128, splits); block 128 = 4 warps (2m x 2n), warp tile 64x64.
// BK=32, cp.async double buffered, ldmatrix fragments.
// SPLIT: z writes its own partial buffer. bias added if !SPLIT.
#define BMM 128
#define BNN 128
#define BKC 32
#define SROWB 80                       // padded row: 40 bf16 = 80 bytes
#define BUFB  (128 * SROWB)            // 10240 bytes per buffer

template<bool SPLIT>
__global__ void __launch_bounds__(128) mma_gemm(
    const __nv_bfloat16* __restrict__ A, int lda,
    const __nv_bfloat16* __restrict__ W, int ldw,
    const float* __restrict__ bias,
    float* __restrict__ C, int ldc,
    int chunks, int strideZ)
{
    __shared__ __nv_bfloat16 As[2][128][40];
    __shared__ __nv_bfloat16 Ws[2][128][40];

    const int tid = threadIdx.x;
    const int wid = tid >> 5, lane = tid & 31;
    const int wm = wid & 1, wn = wid >> 1;
    const int g = lane >> 2, t4 = lane & 3;

    const int rowBase = blockIdx.x * BMM, colBase = blockIdx.y * BNN;
    const long kBase = (long)blockIdx.z * chunks * BKC;
    if (SPLIT) C += (size_t)blockIdx.z * strideZ;

    float acc[4][8][4];
#pragma unroll
    for (int i = 0; i < 4; i++)
#pragma unroll
        for (int j = 0; j < 8; j++)
#pragma unroll
            for (int v = 0; v < 4; v++) acc[i][j][v] = 0.0f;

    // cp.async thread mapping: 4 passes of (row = tid>>2 + 32p, seg = tid&3)
    const int lrow = tid >> 2, lseg = tid & 3;
    const __nv_bfloat16* aSrc = A + (size_t)(rowBase + lrow) * lda + lseg * 8;
    const __nv_bfloat16* wSrc = W + (size_t)(colBase + lrow) * ldw + lseg * 8;
    const uint32_t aDst0 = smem_u32(&As[0][lrow][lseg * 8]);
    const uint32_t wDst0 = smem_u32(&Ws[0][lrow][lseg * 8]);

    // ldmatrix lane addressing
    // A quads: (m0-7,k0-7),(m8-15,k0-7),(m0-7,k8-15),(m8-15,k8-15)
    const int aFragRow = wm * 64 + (lane & 15);
    const uint32_t aFragB0 = smem_u32(&As[0][aFragRow][0]) + ((lane >> 4) << 4);
    // B quads: (n0-7,k0-7),(n0-7,k8-15),(n8-15,k0-7),(n8-15,k8-15)
    const int bFragRow = wn * 64 + (((lane >> 4) << 3) | (lane & 7));
    const uint32_t bFragB0 = smem_u32(&Ws[0][bFragRow][0]) + ((lane & 8) << 1);

    // prime chunk 0
    {
        const long k0 = kBase;
#pragma unroll
        for (int p = 0; p < 4; p++) {
            CP16(aDst0 + p * (32 * SROWB), (const void*)(aSrc + k0 + (size_t)p * 32 * lda));
            CP16(wDst0 + p * (32 * SROWB), (const void*)(wSrc + k0 + (size_t)p * 32 * ldw));
        }
        CP_COMMIT();
    }

    for (int c = 0; c < chunks; ++c) {
        const int buf = c & 1;
        if (c + 1 < chunks) {
            const long k0 = kBase + (long)(c + 1) * BKC;
            const uint32_t ad = aDst0 + (buf ^ 1) * BUFB;
            const uint32_t wd = wDst0 + (buf ^ 1) * BUFB;
#pragma unroll
            for (int p = 0; p < 4; p++) {
                CP16(ad + p * (32 * SROWB), (const void*)(aSrc + k0 + (size_t)p * 32 * lda));
                CP16(wd + p * (32 * SROWB), (const void*)(wSrc + k0 + (size_t)p * 32 * ldw));
            }
            CP_COMMIT();
            CP_WAIT(1);
        } else {
            CP_WAIT(0);
        }
        __syncthreads();

#pragma unroll
        for (int ks = 0; ks < 2; ks++) {
            uint32_t af[4][4], bf[8][2];
#pragma unroll
            for (int mt = 0; mt < 4; mt++) {
                uint32_t addr = aFragB0 + buf * BUFB + mt * (16 * SROWB) + ks * 32;
                LDMX4(af[mt][0], af[mt][1], af[mt][2], af[mt][3], addr);
            }
#pragma unroll
            for (int nt = 0; nt < 4; nt++) {
                uint32_t addr = bFragB0 + buf * BUFB + nt * (16 * SROWB) + ks * 32;
                LDMX4(bf[2 * nt][0], bf[2 * nt][1], bf[2 * nt + 1][0], bf[2 * nt + 1][1], addr);
            }
#pragma unroll
            for (int mt = 0; mt < 4; mt++)
#pragma unroll
                for (int j = 0; j < 8; j++)
                    mma16816(acc[mt][j], af[mt], bf[j]);
        }
        __syncthreads();
    }

    // epilogue
    const int row0 = rowBase + wm * 64;
    const int col0 = colBase + wn * 64;
#pragma unroll
    for (int mt = 0; mt < 4; mt++) {
#pragma unroll
        for (int j = 0; j < 8; j++) {
            const int r = row0 + mt * 16 + g;
            const int cc = col0 + j * 8 + 2 * t4;
            float2 v0 = make_float2(acc[mt][j][0], acc[mt][j][1]);
            float2 v1 = make_float2(acc[mt][j][2], acc[mt][j][3]);
            if (!SPLIT) {
                float2 bb = *(const float2*)(bias + cc);
                v0.x += bb.x; v0.y += bb.y;
                v1.x += bb.x; v1.y += bb.y;
            }
            *(float2*)(C + (size_t)r * ldc + cc) = v0;
            *(float2*)(C + (size_t)(r + 8) * ldc + cc) = v1;
        }
    }
}

// ---------------- setup: convert all weights + nh to split-bf16, zero out[0] ---
#define S0 (H_ENC * H_ENC)     // W_att halves (handled together)
#define S1 (G4 * KX)           // Wg
#define S2 (VOCAB * H_ENC)     // W_out
#define S3 (NTOT * H_ENC)      // nh
__global__ void __launch_bounds__(256) k_convert(
    const float* __restrict__ W_att, const float* __restrict__ W_ih,
    const float* __restrict__ W_hh, const float* __restrict__ W_out,
    const float* __restrict__ nh,
    const float* __restrict__ b_ih, const float* __restrict__ b_hh,
    float* __restrict__ out0)
{
    const int total = S0 + S1 + S2 + S3;
    int gid = blockIdx.x * blockDim.x + threadIdx.x;
    if (gid < G4) g_bg[gid] = b_ih[gid] + b_hh[gid];
    for (int i = gid; i < BV; i += gridDim.x * blockDim.x) out0[i] = 0.0f;
    for (int idx = gid; idx < total; idx += gridDim.x * blockDim.x) {
        if (idx < S0) {
            int n = idx >> 9, k = idx & 511;
            __nv_bfloat16 hi, lo;
            split2(W_att[n * 1024 + k], hi, lo);
            g_Wab1[n * KP_H + k] = hi; g_Wab1[n * KP_H + 512 + k] = lo;
            g_Wab1[n * KP_H + 1024 + k] = hi;
            split2(W_att[n * 1024 + 512 + k], hi, lo);
            g_Wab2[n * KP_H + k] = hi; g_Wab2[n * KP_H + 512 + k] = lo;
            g_Wab2[n * KP_H + 1024 + k] = hi;
        } else if (idx < S0 + S1) {
            int t = idx - S0;
            int n = t / KX, k = t - n * KX;
            float v = (k < 768) ? W_ih[n * 768 + k] : W_hh[n * 512 + (k - 768)];
            __nv_bfloat16 hi, lo;
            split2(v, hi, lo);
            g_Wgb[(size_t)n * KP_X + k] = hi;
            g_Wgb[(size_t)n * KP_X + 1280 + k] = lo;
            g_Wgb[(size_t)n * KP_X + 2560 + k] = hi;
        } else if (idx < S0 + S1 + S2) {
            int t = idx - S0 - S1;
            int n = t >> 9, k = t & 511;
            __nv_bfloat16 hi, lo;
            split2(W_out[(size_t)n * 512 + k], hi, lo);
            g_Wob[(size_t)n * KP_H + k] = hi;
            g_Wob[(size_t)n * KP_H + 512 + k] = lo;
            g_Wob[(size_t)n * KP_H + 1024 + k] = hi;
        } else {
            int t = idx - S0 - S1 - S2;
            int n = t >> 9, k = t & 511;
            __nv_bfloat16 hi, lo;
            split2(nh[(size_t)n * 512 + k], hi, lo);
            g_nhb[(size_t)n * KP_H + k] = hi;        // A layout: [hi | hi | lo]
            g_nhb[(size_t)n * KP_H + 512 + k] = hi;
            g_nhb[(size_t)n * KP_H + 1024 + k] = lo;
        }
    }
}

__global__ void __launch_bounds__(256) k_init_state(
    const float* __restrict__ nh, const int* __restrict__ root,
    const int* __restrict__ labels, const float* __restrict__ emb)
{
    int idx = blockIdx.x * blockDim.x + threadIdx.x;   // 65536
    int b = idx >> 9, j = idx & 511;
    float h0 = nh[(size_t)root[b] * H_ENC + j];
    g_c[idx] = 0.0f;
    __nv_bfloat16 hi, lo;
    split2(h0, hi, lo);
    g_hb[b * KP_H + j] = hi; g_hb[b * KP_H + 512 + j] = hi; g_hb[b * KP_H + 1024 + j] = lo;
    g_xb[b * KP_X + 768 + j] = hi; g_xb[b * KP_X + 2048 + j] = hi; g_xb[b * KP_X + 3328 + j] = lo;
    if (idx < BATCH * H_DEC) {
        int be = idx >> 8, je = idx & 255;
        float e = emb[(size_t)labels[be] * H_DEC + je];
        split2(e, hi, lo);
        g_xb[be * KP_X + je] = hi; g_xb[be * KP_X + 1280 + je] = hi; g_xb[be * KP_X + 2560 + je] = lo;
    }
}

// ---------------- per-step kernels ----------------
__global__ void __launch_bounds__(256) k_attention(
    const float* __restrict__ nh, const int* __restrict__ root,
    const float* __restrict__ v_att)
{
    const int b = blockIdx.x;
    const int tid = threadIdx.x, lid = tid & 31, wid = tid >> 5;
    __shared__ float sQ[H_ENC], sV[H_ENC];
    __shared__ float sred[8];
    __shared__ float s_m, s_invz;
    __shared__ float wbuf[256];

    const int s0 = root[b];
    const int s1 = (b == BATCH - 1) ? NTOT : root[b + 1];

    for (int j = tid; j < H_ENC; j += 256) {
        float q = 0.0f;
#pragma unroll
        for (int z = 0; z < QH_SPLITS; z++)
            q += g_QhP[z * (BATCH * H_ENC) + b * H_ENC + j];
        sQ[j] = q;
        sV[j] = v_att[j];
    }
    __syncthreads();

    const float2* sQ2 = (const float2*)sQ;
    const float2* sV2 = (const float2*)sV;
    for (int n = s0 + wid; n < s1; n += 8) {
        const float2* Pr2 = (const float2*)(g_P + (size_t)n * H_ENC);
        float acc = 0.0f;
#pragma unroll
        for (int it = 0; it < 8; ++it) {
            int j = lid + it * 32;
            float2 p = Pr2[j], q = sQ2[j], vv = sV2[j];
            acc += vv.x * fast_tanh(p.x + q.x) + vv.y * fast_tanh(p.y + q.y);
        }
#pragma unroll
        for (int o = 16; o; o >>= 1) acc += __shfl_xor_sync(0xffffffffu, acc, o);
        if (lid == 0) g_score[n] = acc;
    }
    __syncthreads();

    float m = -3.402823466e38f;
    for (int n = s0 + tid; n < s1; n += 256) m = fmaxf(m, g_score[n]);
#pragma unroll
    for (int o = 16; o; o >>= 1) m = fmaxf(m, __shfl_xor_sync(0xffffffffu, m, o));
    if (lid == 0) sred[wid] = m;
    __syncthreads();
    if (tid == 0) {
        float mm = sred[0];
        for (int w = 1; w < 8; w++) mm = fmaxf(mm, sred[w]);
        s_m = mm;
    }
    __syncthreads();
    m = s_m;

    float z = 0.0f;
    for (int n = s0 + tid; n < s1; n += 256) z += __expf(g_score[n] - m);
#pragma unroll
    for (int o = 16; o; o >>= 1) z += __shfl_xor_sync(0xffffffffu, z, o);
    if (lid == 0) sred[wid] = z;
    __syncthreads();
    if (tid == 0) {
        float zz = 0.0f;
        for (int w = 0; w < 8; w++) zz += sred[w];
        s_invz = 1.0f / zz;
    }
    __syncthreads();
    const float invz = s_invz;

    float2 a = make_float2(0.0f, 0.0f);
    for (int cs = s0; cs < s1; cs += 256) {
        const int cn = min(256, s1 - cs);
        __syncthreads();
        if (tid < cn) wbuf[tid] = __expf(g_score[cs + tid] - m);
        __syncthreads();
#pragma unroll 4
        for (int i = 0; i < cn; i++) {
            float w = wbuf[i];
            float2 r = *(const float2*)(nh + (size_t)(cs + i) * H_ENC + 2 * tid);
            a.x += w * r.x;
            a.y += w * r.y;
        }
    }
    a.x *= invz; a.y *= invz;
    // write attended (cols 256..768 of x) in split-bf16
    const int c0 = 2 * tid;
    __nv_bfloat16 hi, lo;
    split2(a.x, hi, lo);
    g_xb[b * KP_X + 256 + c0] = hi; g_xb[b * KP_X + 1536 + c0] = hi; g_xb[b * KP_X + 2816 + c0] = lo;
    split2(a.y, hi, lo);
    g_xb[b * KP_X + 257 + c0] = hi; g_xb[b * KP_X + 1537 + c0] = hi; g_xb[b * KP_X + 2817 + c0] = lo;
}

__global__ void __launch_bounds__(256) k_lstm() {
    const int idx = blockIdx.x * blockDim.x + threadIdx.x;   // 65536
    const int b = idx >> 9, j = idx & 511;
    float ig = g_bg[j], fg = g_bg[512 + j], gg = g_bg[1024 + j], og = g_bg[1536 + j];
#pragma unroll
    for (int z = 0; z < GT_SPLITS; z++) {
        const float* gr = g_gatesP + (size_t)z * (BATCH * G4) + b * G4 + j;
        ig += gr[0]; fg += gr[512]; gg += gr[1024]; og += gr[1536];
    }
    float c = fsigm(fg) * g_c[idx] + fsigm(ig) * fast_tanh(gg);
    g_c[idx] = c;
    float h = fsigm(og) * fast_tanh(c);
    __nv_bfloat16 hi, lo;
    split2(h, hi, lo);
    g_hb[b * KP_H + j] = hi; g_hb[b * KP_H + 512 + j] = hi; g_hb[b * KP_H + 1024 + j] = lo;
    g_xb[b * KP_X + 768 + j] = hi; g_xb[b * KP_X + 2048 + j] = hi; g_xb[b * KP_X + 3328 + j] = lo;
}

__global__ void __launch_bounds__(256) k_out(
    const float* __restrict__ b_out, const float* __restrict__ emb,
    float* __restrict__ slab)
{
    const int b = blockIdx.x, tid = threadIdx.x;
    float* row = slab + (size_t)b * VOCAB;
    float best = -3.402823466e38f;
    int bi = VOCAB;
    for (int j = tid; j < VOCAB; j += 256) {
        float v = b_out[j];
#pragma unroll
        for (int z = 0; z < LG_SPLITS; z++)
            v += g_logitsP[(size_t)z * BV + (size_t)b * VOCAB + j];
        row[j] = v;
        if (v > best) { best = v; bi = j; }
    }
    __shared__ float sv[256];
    __shared__ int si[256];
    __shared__ int s_cur;
    sv[tid] = best; si[tid] = bi;
    __syncthreads();
    for (int s = 128; s; s >>= 1) {
        if (tid < s) {
            float v2 = sv[tid + s]; int i2 = si[tid + s];
            if (v2 > sv[tid] || (v2 == sv[tid] && i2 < si[tid])) { sv[tid] = v2; si[tid] = i2; }
        }
        __syncthreads();
    }
    if (tid == 0) s_cur = si[0];
    __syncthreads();
    float e = emb[(size_t)s_cur * H_DEC + tid];   // H_DEC == 256 == blockDim
    __nv_bfloat16 hi, lo;
    split2(e, hi, lo);
    g_xb[b * KP_X + tid] = hi; g_xb[b * KP_X + 1280 + tid] = hi; g_xb[b * KP_X + 2560 + tid] = lo;
}

// ---------------- launch ----------------
extern "C" void kernel_launch(void* const* d_in, const int* in_sizes, int n_in,
                              void* d_out, int out_size) {
    const float* nh    = (const float*)d_in[0];
    const int*   labels= (const int*)  d_in[1];
    const int*   root  = (const int*)  d_in[2];
    const float* emb   = (const float*)d_in[3];
    const float* W_att = (const float*)d_in[4];
    const float* b_att = (const float*)d_in[5];
    const float* v_att = (const float*)d_in[6];
    const float* W_ih  = (const float*)d_in[7];
    const float* W_hh  = (const float*)d_in[8];
    const float* b_ih  = (const float*)d_in[9];
    const float* b_hh  = (const float*)d_in[10];
    const float* W_out = (const float*)d_in[11];
    const float* b_out = (const float*)d_in[12];
    float* out = (float*)d_out;

    float *pP, *pQhP, *pGatesP, *pLogitsP;
    __nv_bfloat16 *pHb, *pXb, *pNhb, *pWab1, *pWab2, *pWgb, *pWob;
    cudaGetSymbolAddress((void**)&pP, g_P);
    cudaGetSymbolAddress((void**)&pQhP, g_QhP);
    cudaGetSymbolAddress((void**)&pGatesP, g_gatesP);
    cudaGetSymbolAddress((void**)&pLogitsP, g_logitsP);
    cudaGetSymbolAddress((void**)&pHb, g_hb);
    cudaGetSymbolAddress((void**)&pXb, g_xb);
    cudaGetSymbolAddress((void**)&pNhb, g_nhb);
    cudaGetSymbolAddress((void**)&pWab1, g_Wab1);
    cudaGetSymbolAddress((void**)&pWab2, g_Wab2);
    cudaGetSymbolAddress((void**)&pWgb, g_Wgb);
    cudaGetSymbolAddress((void**)&pWob, g_Wob);

    // ---- setup (launch #4 = first Qh GEMM -> ncu -s 5 lands on a per-step GEMM)
    k_convert<<<2048, 256>>>(W_att, W_ih, W_hh, W_out, nh, b_ih, b_hh, out);
    k_init_state<<<256, 256>>>(nh, root, labels, emb);
    // P = nh @ W_att[:,512:]^T + b_att   (step-invariant, fp32 out)
    mma_gemm<false><<<dim3(NTOT / 128, H_ENC / 128, 1), 128>>>(
        pNhb, KP_H, pWab2, KP_H, b_att, pP, H_ENC, KP_H / BKC, 0);

    // ---- decode steps ----
    for (int t = 1; t < LSEQ; t++) {
        float* slab = out + (size_t)t * BV;
        // Qh partials = h @ W_att[:,:512]^T
        mma_gemm<true><<<dim3(1, H_ENC / 128, QH_SPLITS), 128>>>(
            pHb, KP_H, pWab1, KP_H, nullptr, pQhP, H_ENC,
            KP_H / BKC / QH_SPLITS, BATCH * H_ENC);
        k_attention<<<BATCH, 256>>>(nh, root, v_att);
        // gates partials = x @ [W_ih|W_hh]^T
        mma_gemm<true><<<dim3(1, G4 / 128, GT_SPLITS), 128>>>(
            pXb, KP_X, pWgb, KP_X, nullptr, pGatesP, G4,
            KP_X / BKC / GT_SPLITS, BATCH * G4);
        k_lstm<<<256, 256>>>();
        // logits partials = h @ W_out^T
        mma_gemm<true><<<dim3(1, VOCAB / 128, LG_SPLITS), 128>>>(
            pHb, KP_H, pWob, KP_H, nullptr, pLogitsP, VOCAB,
            KP_H / BKC / LG_SPLITS, BV);
        k_out<<<BATCH, 256>>>(b_out, emb, slab);
    }
}

// round 7
// speedup vs baseline: 1.7538x; 1.1271x over previous
#include <cuda_runtime.h>
#include <cuda_bf16.h>
#include <cstdint>

#define H_ENC 512
#define H_DEC 256
#define VOCAB 8192
#define BATCH 128
#define NTOT  16384
#define LSEQ  13
#define KX    1280           // H_DEC + H_ENC (attended) + H_ENC (h)
#define G4    2048           // 4*H_ENC
#define BV    (BATCH*VOCAB)  // 1048576

#define KP_H  1536           // 3*512  (split-K' for K=512 operands)
#define KP_X  3840           // 3*1280 (split-K' for x)

#define NQO   (H_ENC + VOCAB)        // 8704: [Qh | logits] combined N
#define QL_SPLITS 4
#define GT_SPLITS 10
#define PSTRIDE (BATCH * NQO)        // per-split stride in g_qlP

// ---------------- device scratch (no cudaMalloc allowed) ----------------
__device__ float g_P[NTOT * H_ENC];                 // 32 MB fp32: nh @ W_att2^T + b_att
__device__ float g_c[BATCH * H_ENC];
__device__ float g_score[NTOT];
__device__ float g_bg[G4];                          // b_ih + b_hh
__device__ float g_qlP[QL_SPLITS * BATCH * NQO];    // [Qh | logits] split-K partials
__device__ float g_gatesP[GT_SPLITS * BATCH * G4];
// split-bf16 interleaved operands: [hi | hi | lo] along K'
__device__ __nv_bfloat16 g_hb [BATCH * KP_H];       // h
__device__ __nv_bfloat16 g_xb [BATCH * KP_X];       // x = [emb | attended | h]
__device__ __nv_bfloat16 g_nhb[NTOT * KP_H];        // node_hidden_states
// split-bf16 interleaved weights: [hi | lo | hi] along K'
__device__ __nv_bfloat16 g_Wab2[H_ENC * KP_H];      // W_att[:, 512:]  (P)
__device__ __nv_bfloat16 g_Wqo [NQO * KP_H];        // [W_att[:,:512] ; W_out]
__device__ __nv_bfloat16 g_Wgb [G4 * KP_X];         // [W_ih | W_hh]

// ---------------- math helpers ----------------
__device__ __forceinline__ float fast_tanh(float x) {
    float e = __expf(2.0f * x), r;
    asm("rcp.approx.f32 %0, %1;" : "=f"(r) : "f"(e + 1.0f));
    return 1.0f - 2.0f * r;
}
__device__ __forceinline__ float fsigm(float x) {
    float e = __expf(-x), r;
    asm("rcp.approx.f32 %0, %1;" : "=f"(r) : "f"(e + 1.0f));
    return r;
}
__device__ __forceinline__ void split2(float v, __nv_bfloat16& hi, __nv_bfloat16& lo) {
    hi = __float2bfloat16(v);
    lo = __float2bfloat16(v - __bfloat162float(hi));
}
__device__ __forceinline__ uint32_t smem_u32(const void* p) {
    uint32_t a;
    asm("{ .reg .u64 t; cvta.to.shared.u64 t, %1; cvt.u32.u64 %0, t; }"
        : "=r"(a) : "l"(p));
    return a;
}
__device__ __forceinline__ void mma16816(float* d, const uint32_t* a, const uint32_t* b) {
    asm volatile(
        "mma.sync.aligned.m16n8k16.row.col.f32.bf16.bf16.f32 "
        "{%0,%1,%2,%3}, {%4,%5,%6,%7}, {%8,%9}, {%0,%1,%2,%3};"
        : "+f"(d[0]), "+f"(d[1]), "+f"(d[2]), "+f"(d[3])
        : "r"(a[0]), "r"(a[1]), "r"(a[2]), "r"(a[3]), "r"(b[0]), "r"(b[1]));
}
#define LDMX4(r0, r1, r2, r3, addr) \
    asm volatile("ldmatrix.sync.aligned.m8n8.x4.shared.b16 {%0,%1,%2,%3}, [%4];" \
        : "=r"(r0), "=r"(r1), "=r"(r2), "=r"(r3) : "r"(addr))
#define CP16(dst, src) \
    asm volatile("cp.async.cg.shared.global [%0], [%1], 16;" :: "r"(dst), "l"(src))
#define CP_COMMIT() asm volatile("cp.async.commit_group;" ::: "memory")
#define CP_WAIT(n)  asm volatile("cp.async.wait_group %0;" :: "n"(n) : "memory")

// ---------------- HMMA GEMM: C[M,N] = A'[M,K'] @ W'[N,K']^T (bf16->fp32) ------
// grid (M/128, N/128, splits); block 128 = 4 warps (2m x 2n), warp tile 64x64.
// BK=32, 3-stage cp.async ring, ldmatrix fragments. Dynamic smem 61440 B.
// SPLIT: z writes its own partial buffer. bias added if !SPLIT.
#define BMM 128
#define BNN 128
#define BKC 32
#define SROWB 80                       // padded row: 40 bf16 = 80 bytes
#define BUFB  (128 * SROWB)            // 10240 bytes per stage buffer
#define WOFF  (3 * BUFB)               // Ws region offset
#define DSMEM (6 * BUFB)               // 61440 bytes

template<bool SPLIT>
__global__ void __launch_bounds__(128) mma_gemm(
    const __nv_bfloat16* __restrict__ A, int lda,
    const __nv_bfloat16* __restrict__ W, int ldw,
    const float* __restrict__ bias,
    float* __restrict__ C, int ldc,
    int chunks, int strideZ)
{
    extern __shared__ char dsm[];
    const uint32_t sbase = smem_u32(dsm);

    const int tid = threadIdx.x;
    const int wid = tid >> 5, lane = tid & 31;
    const int wm = wid & 1, wn = wid >> 1;
    const int g = lane >> 2, t4 = lane & 3;

    const int rowBase = blockIdx.x * BMM, colBase = blockIdx.y * BNN;
    const long kBase = (long)blockIdx.z * chunks * BKC;
    if (SPLIT) C += (size_t)blockIdx.z * strideZ;

    float acc[4][8][4];
#pragma unroll
    for (int i = 0; i < 4; i++)
#pragma unroll
        for (int j = 0; j < 8; j++)
#pragma unroll
            for (int v = 0; v < 4; v++) acc[i][j][v] = 0.0f;

    // cp.async thread mapping: 4 passes of (row = tid>>2 + 32p, seg = tid&3)
    const int lrow = tid >> 2, lseg = tid & 3;
    const __nv_bfloat16* aSrc = A + (size_t)(rowBase + lrow) * lda + lseg * 8;
    const __nv_bfloat16* wSrc = W + (size_t)(colBase + lrow) * ldw + lseg * 8;
    const uint32_t aDst0 = sbase + lrow * SROWB + lseg * 16;
    const uint32_t wDst0 = sbase + WOFF + lrow * SROWB + lseg * 16;

    // ldmatrix lane addressing
    const int aFragRow = wm * 64 + (lane & 15);
    const uint32_t aFragB0 = sbase + aFragRow * SROWB + ((lane >> 4) << 4);
    const int bFragRow = wn * 64 + (((lane >> 4) << 3) | (lane & 7));
    const uint32_t bFragB0 = sbase + WOFF + bFragRow * SROWB + ((lane & 8) << 1);

    // prime 2 chunks
    const int pre = (chunks < 2) ? chunks : 2;
    for (int i = 0; i < pre; i++) {
        const long k0 = kBase + (long)i * BKC;
#pragma unroll
        for (int p = 0; p < 4; p++) {
            CP16(aDst0 + i * BUFB + p * (32 * SROWB), (const void*)(aSrc + k0 + (size_t)p * 32 * lda));
            CP16(wDst0 + i * BUFB + p * (32 * SROWB), (const void*)(wSrc + k0 + (size_t)p * 32 * ldw));
        }
        CP_COMMIT();
    }

    for (int c = 0; c < chunks; ++c) {
        const int buf = c % 3;
        if (c + 2 < chunks) {
            const int nb = (c + 2) % 3;
            const long k0 = kBase + (long)(c + 2) * BKC;
#pragma unroll
            for (int p = 0; p < 4; p++) {
                CP16(aDst0 + nb * BUFB + p * (32 * SROWB), (const void*)(aSrc + k0 + (size_t)p * 32 * lda));
                CP16(wDst0 + nb * BUFB + p * (32 * SROWB), (const void*)(wSrc + k0 + (size_t)p * 32 * ldw));
            }
            CP_COMMIT();
            CP_WAIT(2);
        } else if (c + 1 < chunks) {
            CP_WAIT(1);
        } else {
            CP_WAIT(0);
        }
        __syncthreads();

#pragma unroll
        for (int ks = 0; ks < 2; ks++) {
            uint32_t af[4][4], bf[8][2];
#pragma unroll
            for (int mt = 0; mt < 4; mt++) {
                uint32_t addr = aFragB0 + buf * BUFB + mt * (16 * SROWB) + ks * 32;
                LDMX4(af[mt][0], af[mt][1], af[mt][2], af[mt][3], addr);
            }
#pragma unroll
            for (int nt = 0; nt < 4; nt++) {
                uint32_t addr = bFragB0 + buf * BUFB + nt * (16 * SROWB) + ks * 32;
                LDMX4(bf[2 * nt][0], bf[2 * nt][1], bf[2 * nt + 1][0], bf[2 * nt + 1][1], addr);
            }
#pragma unroll
            for (int mt = 0; mt < 4; mt++)
#pragma unroll
                for (int j = 0; j < 8; j++)
                    mma16816(acc[mt][j], af[mt], bf[j]);
        }
        __syncthreads();
    }

    // epilogue
    const int row0 = rowBase + wm * 64;
    const int col0 = colBase + wn * 64;
#pragma unroll
    for (int mt = 0; mt < 4; mt++) {
#pragma unroll
        for (int j = 0; j < 8; j++) {
            const int r = row0 + mt * 16 + g;
            const int cc = col0 + j * 8 + 2 * t4;
            float2 v0 = make_float2(acc[mt][j][0], acc[mt][j][1]);
            float2 v1 = make_float2(acc[mt][j][2], acc[mt][j][3]);
            if (!SPLIT) {
                float2 bb = *(const float2*)(bias + cc);
                v0.x += bb.x; v0.y += bb.y;
                v1.x += bb.x; v1.y += bb.y;
            }
            *(float2*)(C + (size_t)r * ldc + cc) = v0;
            *(float2*)(C + (size_t)(r + 8) * ldc + cc) = v1;
        }
    }
}

// ---------------- setup: convert weights + nh, init state, zero out[0] ---------
#define S0 (H_ENC * H_ENC)     // W_att halves (handled together)
#define S1 (G4 * KX)           // Wg
#define S2 (VOCAB * H_ENC)     // W_out
#define S3 (NTOT * H_ENC)      // nh
__global__ void __launch_bounds__(256) k_setup(
    const float* __restrict__ W_att, const float* __restrict__ W_ih,
    const float* __restrict__ W_hh, const float* __restrict__ W_out,
    const float* __restrict__ nh,
    const float* __restrict__ b_ih, const float* __restrict__ b_hh,
    const int* __restrict__ root, const int* __restrict__ labels,
    const float* __restrict__ emb, float* __restrict__ out0)
{
    const int total = S0 + S1 + S2 + S3;
    int gid = blockIdx.x * blockDim.x + threadIdx.x;
    if (gid < G4) g_bg[gid] = b_ih[gid] + b_hh[gid];
    for (int i = gid; i < BV; i += gridDim.x * blockDim.x) out0[i] = 0.0f;

    // init h, c, x (emb | - | h)
    if (gid < BATCH * H_ENC) {
        int b = gid >> 9, j = gid & 511;
        float h0 = nh[(size_t)root[b] * H_ENC + j];
        g_c[gid] = 0.0f;
        __nv_bfloat16 hi, lo;
        split2(h0, hi, lo);
        g_hb[b * KP_H + j] = hi; g_hb[b * KP_H + 512 + j] = hi; g_hb[b * KP_H + 1024 + j] = lo;
        g_xb[b * KP_X + 768 + j] = hi; g_xb[b * KP_X + 2048 + j] = hi; g_xb[b * KP_X + 3328 + j] = lo;
        if (gid < BATCH * H_DEC) {
            int be = gid >> 8, je = gid & 255;
            float e = emb[(size_t)labels[be] * H_DEC + je];
            split2(e, hi, lo);
            g_xb[be * KP_X + je] = hi; g_xb[be * KP_X + 1280 + je] = hi; g_xb[be * KP_X + 2560 + je] = lo;
        }
    }

    for (int idx = gid; idx < total; idx += gridDim.x * blockDim.x) {
        if (idx < S0) {
            int n = idx >> 9, k = idx & 511;
            __nv_bfloat16 hi, lo;
            split2(W_att[n * 1024 + k], hi, lo);      // W_att1 -> Wqo rows 0..511
            g_Wqo[(size_t)n * KP_H + k] = hi;
            g_Wqo[(size_t)n * KP_H + 512 + k] = lo;
            g_Wqo[(size_t)n * KP_H + 1024 + k] = hi;
            split2(W_att[n * 1024 + 512 + k], hi, lo); // W_att2 -> P weights
            g_Wab2[n * KP_H + k] = hi; g_Wab2[n * KP_H + 512 + k] = lo;
            g_Wab2[n * KP_H + 1024 + k] = hi;
        } else if (idx < S0 + S1) {
            int t = idx - S0;
            int n = t / KX, k = t - n * KX;
            float v = (k < 768) ? W_ih[n * 768 + k] : W_hh[n * 512 + (k - 768)];
            __nv_bfloat16 hi, lo;
            split2(v, hi, lo);
            g_Wgb[(size_t)n * KP_X + k] = hi;
            g_Wgb[(size_t)n * KP_X + 1280 + k] = lo;
            g_Wgb[(size_t)n * KP_X + 2560 + k] = hi;
        } else if (idx < S0 + S1 + S2) {
            int t = idx - S0 - S1;
            int n = t >> 9, k = t & 511;
            __nv_bfloat16 hi, lo;
            split2(W_out[(size_t)n * 512 + k], hi, lo); // W_out -> Wqo rows 512..8703
            g_Wqo[(size_t)(512 + n) * KP_H + k] = hi;
            g_Wqo[(size_t)(512 + n) * KP_H + 512 + k] = lo;
            g_Wqo[(size_t)(512 + n) * KP_H + 1024 + k] = hi;
        } else {
            int t = idx - S0 - S1 - S2;
            int n = t >> 9, k = t & 511;
            __nv_bfloat16 hi, lo;
            split2(nh[(size_t)n * 512 + k], hi, lo);
            g_nhb[(size_t)n * KP_H + k] = hi;        // A layout: [hi | hi | lo]
            g_nhb[(size_t)n * KP_H + 512 + k] = hi;
            g_nhb[(size_t)n * KP_H + 1024 + k] = lo;
        }
    }
}

// ---------------- fused attention(step t) + out(step t-1) ----------------------
// blocks 0..127: attention for tree b (if doAtt). blocks 128..255: logits
// reduce + slab store + argmax + emb gather for tree b-128 (if slabPrev).
__global__ void __launch_bounds__(256) k_attout(
    const float* __restrict__ nh, const int* __restrict__ root,
    const float* __restrict__ v_att, const float* __restrict__ b_out,
    const float* __restrict__ emb, float* __restrict__ slabPrev, int doAtt)
{
    const int tid = threadIdx.x, lid = tid & 31, wid = tid >> 5;

    if (blockIdx.x < BATCH) {
        if (!doAtt) return;
        const int b = blockIdx.x;
        __shared__ float sQ[H_ENC], sV[H_ENC];
        __shared__ float sred[8];
        __shared__ float s_m, s_invz;
        __shared__ float wbuf[256];

        const int s0 = root[b];
        const int s1 = (b == BATCH - 1) ? NTOT : root[b + 1];

        for (int j = tid; j < H_ENC; j += 256) {
            float q = 0.0f;
#pragma unroll
            for (int z = 0; z < QL_SPLITS; z++)
                q += g_qlP[(size_t)z * PSTRIDE + (size_t)b * NQO + j];
            sQ[j] = q;
            sV[j] = v_att[j];
        }
        __syncthreads();

        const float2* sQ2 = (const float2*)sQ;
        const float2* sV2 = (const float2*)sV;
        for (int n = s0 + wid; n < s1; n += 8) {
            const float2* Pr2 = (const float2*)(g_P + (size_t)n * H_ENC);
            float acc = 0.0f;
#pragma unroll
            for (int it = 0; it < 8; ++it) {
                int j = lid + it * 32;
                float2 p = Pr2[j], q = sQ2[j], vv = sV2[j];
                acc += vv.x * fast_tanh(p.x + q.x) + vv.y * fast_tanh(p.y + q.y);
            }
#pragma unroll
            for (int o = 16; o; o >>= 1) acc += __shfl_xor_sync(0xffffffffu, acc, o);
            if (lid == 0) g_score[n] = acc;
        }
        __syncthreads();

        float m = -3.402823466e38f;
        for (int n = s0 + tid; n < s1; n += 256) m = fmaxf(m, g_score[n]);
#pragma unroll
        for (int o = 16; o; o >>= 1) m = fmaxf(m, __shfl_xor_sync(0xffffffffu, m, o));
        if (lid == 0) sred[wid] = m;
        __syncthreads();
        if (tid == 0) {
            float mm = sred[0];
            for (int w = 1; w < 8; w++) mm = fmaxf(mm, sred[w]);
            s_m = mm;
        }
        __syncthreads();
        m = s_m;

        float z = 0.0f;
        for (int n = s0 + tid; n < s1; n += 256) z += __expf(g_score[n] - m);
#pragma unroll
        for (int o = 16; o; o >>= 1) z += __shfl_xor_sync(0xffffffffu, z, o);
        if (lid == 0) sred[wid] = z;
        __syncthreads();
        if (tid == 0) {
            float zz = 0.0f;
            for (int w = 0; w < 8; w++) zz += sred[w];
            s_invz = 1.0f / zz;
        }
        __syncthreads();
        const float invz = s_invz;

        float2 a = make_float2(0.0f, 0.0f);
        for (int cs = s0; cs < s1; cs += 256) {
            const int cn = min(256, s1 - cs);
            __syncthreads();
            if (tid < cn) wbuf[tid] = __expf(g_score[cs + tid] - m);
            __syncthreads();
#pragma unroll 4
            for (int i = 0; i < cn; i++) {
                float w = wbuf[i];
                float2 r = *(const float2*)(nh + (size_t)(cs + i) * H_ENC + 2 * tid);
                a.x += w * r.x;
                a.y += w * r.y;
            }
        }
        a.x *= invz; a.y *= invz;
        const int c0 = 2 * tid;
        __nv_bfloat16 hi, lo;
        split2(a.x, hi, lo);
        g_xb[b * KP_X + 256 + c0] = hi; g_xb[b * KP_X + 1536 + c0] = hi; g_xb[b * KP_X + 2816 + c0] = lo;
        split2(a.y, hi, lo);
        g_xb[b * KP_X + 257 + c0] = hi; g_xb[b * KP_X + 1537 + c0] = hi; g_xb[b * KP_X + 2817 + c0] = lo;
    } else {
        if (slabPrev == nullptr) return;
        const int b = blockIdx.x - BATCH;
        float* row = slabPrev + (size_t)b * VOCAB;
        float best = -3.402823466e38f;
        int bi = VOCAB;
        for (int j = tid; j < VOCAB; j += 256) {
            float v = b_out[j];
#pragma unroll
            for (int z = 0; z < QL_SPLITS; z++)
                v += g_qlP[(size_t)z * PSTRIDE + (size_t)b * NQO + H_ENC + j];
            row[j] = v;
            if (v > best) { best = v; bi = j; }
        }
        __shared__ float sv[256];
        __shared__ int si[256];
        __shared__ int s_cur;
        sv[tid] = best; si[tid] = bi;
        __syncthreads();
        for (int s = 128; s; s >>= 1) {
            if (tid < s) {
                float v2 = sv[tid + s]; int i2 = si[tid + s];
                if (v2 > sv[tid] || (v2 == sv[tid] && i2 < si[tid])) { sv[tid] = v2; si[tid] = i2; }
            }
            __syncthreads();
        }
        if (tid == 0) s_cur = si[0];
        __syncthreads();
        float e = emb[(size_t)s_cur * H_DEC + tid];   // H_DEC == 256 == blockDim
        __nv_bfloat16 hi, lo;
        split2(e, hi, lo);
        g_xb[b * KP_X + tid] = hi; g_xb[b * KP_X + 1280 + tid] = hi; g_xb[b * KP_X + 2560 + tid] = lo;
    }
}

// fused: gate partial-reduce + bias + LSTM update; writes h, c, and h slot of x
__global__ void __launch_bounds__(256) k_lstm() {
    const int idx = blockIdx.x * blockDim.x + threadIdx.x;   // 65536
    const int b = idx >> 9, j = idx & 511;
    float ig = g_bg[j], fg = g_bg[512 + j], gg = g_bg[1024 + j], og = g_bg[1536 + j];
#pragma unroll
    for (int z = 0; z < GT_SPLITS; z++) {
        const float* gr = g_gatesP + (size_t)z * (BATCH * G4) + b * G4 + j;
        ig += gr[0]; fg += gr[512]; gg += gr[1024]; og += gr[1536];
    }
    float c = fsigm(fg) * g_c[idx] + fsigm(ig) * fast_tanh(gg);
    g_c[idx] = c;
    float h = fsigm(og) * fast_tanh(c);
    __nv_bfloat16 hi, lo;
    split2(h, hi, lo);
    g_hb[b * KP_H + j] = hi; g_hb[b * KP_H + 512 + j] = hi; g_hb[b * KP_H + 1024 + j] = lo;
    g_xb[b * KP_X + 768 + j] = hi; g_xb[b * KP_X + 2048 + j] = hi; g_xb[b * KP_X + 3328 + j] = lo;
}

// ---------------- launch ----------------
extern "C" void kernel_launch(void* const* d_in, const int* in_sizes, int n_in,
                              void* d_out, int out_size) {
    const float* nh    = (const float*)d_in[0];
    const int*   labels= (const int*)  d_in[1];
    const int*   root  = (const int*)  d_in[2];
    const float* emb   = (const float*)d_in[3];
    const float* W_att = (const float*)d_in[4];
    const float* b_att = (const float*)d_in[5];
    const float* v_att = (const float*)d_in[6];
    const float* W_ih  = (const float*)d_in[7];
    const float* W_hh  = (const float*)d_in[8];
    const float* b_ih  = (const float*)d_in[9];
    const float* b_hh  = (const float*)d_in[10];
    const float* W_out = (const float*)d_in[11];
    const float* b_out = (const float*)d_in[12];
    float* out = (float*)d_out;

    float *pP, *pQlP, *pGatesP;
    __nv_bfloat16 *pHb, *pXb, *pNhb, *pWab2, *pWqo, *pWgb;
    cudaGetSymbolAddress((void**)&pP, g_P);
    cudaGetSymbolAddress((void**)&pQlP, g_qlP);
    cudaGetSymbolAddress((void**)&pGatesP, g_gatesP);
    cudaGetSymbolAddress((void**)&pHb, g_hb);
    cudaGetSymbolAddress((void**)&pXb, g_xb);
    cudaGetSymbolAddress((void**)&pNhb, g_nhb);
    cudaGetSymbolAddress((void**)&pWab2, g_Wab2);
    cudaGetSymbolAddress((void**)&pWqo, g_Wqo);
    cudaGetSymbolAddress((void**)&pWgb, g_Wgb);

    cudaFuncSetAttribute(mma_gemm<false>, cudaFuncAttributeMaxDynamicSharedMemorySize, DSMEM);
    cudaFuncSetAttribute(mma_gemm<true>,  cudaFuncAttributeMaxDynamicSharedMemorySize, DSMEM);

    // ---- setup (launch #4 = first k_attout -> ncu -s 5 lands on it)
    k_setup<<<2048, 256>>>(W_att, W_ih, W_hh, W_out, nh, b_ih, b_hh,
                           root, labels, emb, out);
    // P = nh @ W_att[:,512:]^T + b_att   (step-invariant, fp32 out)
    mma_gemm<false><<<dim3(NTOT / 128, H_ENC / 128, 1), 128, DSMEM>>>(
        pNhb, KP_H, pWab2, KP_H, b_att, pP, H_ENC, KP_H / BKC, 0);
    // bootstrap Qh for step 1 (first 512 rows of Wqo)
    mma_gemm<true><<<dim3(1, H_ENC / 128, QL_SPLITS), 128, DSMEM>>>(
        pHb, KP_H, pWqo, KP_H, nullptr, pQlP, NQO,
        KP_H / BKC / QL_SPLITS, PSTRIDE);

    // ---- decode steps: attout -> gates -> lstm -> [Qh|logits] GEMM ----
    for (int t = 1; t < LSEQ; t++) {
        float* slabPrev = (t > 1) ? (out + (size_t)(t - 1) * BV) : nullptr;
        k_attout<<<2 * BATCH, 256>>>(nh, root, v_att, b_out, emb, slabPrev, 1);
        // gates partials = x @ [W_ih|W_hh]^T
        mma_gemm<true><<<dim3(1, G4 / 128, GT_SPLITS), 128, DSMEM>>>(
            pXb, KP_X, pWgb, KP_X, nullptr, pGatesP, G4,
            KP_X / BKC / GT_SPLITS, BATCH * G4);
        k_lstm<<<256, 256>>>();
        // [Qh_{t+1} | logits_t] partials = h @ Wqo^T
        mma_gemm<true><<<dim3(1, NQO / 128, QL_SPLITS), 128, DSMEM>>>(
            pHb, KP_H, pWqo, KP_H, nullptr, pQlP, NQO,
            KP_H / BKC / QL_SPLITS, PSTRIDE);
    }
    // final out for step 12
    k_attout<<<2 * BATCH, 256>>>(nh, root, v_att, b_out, emb,
                                 out + (size_t)(LSEQ - 1) * BV, 0);
}

// round 8
// speedup vs baseline: 2.4066x; 1.3722x over previous
#include <cuda_runtime.h>
#include <cuda_bf16.h>
#include <cstdint>

#define H_ENC 512
#define H_DEC 256
#define VOCAB 8192
#define BATCH 128
#define NTOT  16384
#define LSEQ  13
#define KX    1280           // H_DEC + H_ENC (attended) + H_ENC (h)
#define G4    2048           // 4*H_ENC
#define BV    (BATCH*VOCAB)  // 1048576

#define KP_H  1536           // 3*512  (split-K' for K=512 operands)
#define KP_X  3840           // 3*1280 (split-K' for x)

#define NQO   (H_ENC + VOCAB)        // 8704: [Qh | logits] combined N
#define QL_SPLITS 2
#define GT_SPLITS 8
#define PSTRIDE (BATCH * NQO)        // per-split stride in g_qlP

// ---------------- device scratch (no cudaMalloc allowed) ----------------
__device__ float g_P[NTOT * H_ENC];                 // 32 MB fp32: nh @ W_att2^T + b_att
__device__ float g_c[BATCH * H_ENC];
__device__ float g_score[NTOT];                     // e_n = exp(score_n)
__device__ float g_bg[G4];                          // b_ih + b_hh
__device__ float g_qlP[QL_SPLITS * BATCH * NQO];    // [Qh | logits] split-K partials
__device__ float g_gatesP[GT_SPLITS * BATCH * G4];
// split-bf16 interleaved operands: [hi | hi | lo] along K'
__device__ __nv_bfloat16 g_hb [BATCH * KP_H];       // h
__device__ __nv_bfloat16 g_xb [BATCH * KP_X];       // x = [emb | attended | h]
__device__ __nv_bfloat16 g_nhb[NTOT * KP_H];        // node_hidden_states
// split-bf16 interleaved weights: [hi | lo | hi] along K'
__device__ __nv_bfloat16 g_Wab2[H_ENC * KP_H];      // W_att[:, 512:]  (P)
__device__ __nv_bfloat16 g_Wqo [NQO * KP_H];        // [W_att[:,:512] ; W_out]
__device__ __nv_bfloat16 g_Wgb [G4 * KP_X];         // [W_ih | W_hh]

// ---------------- math helpers ----------------
__device__ __forceinline__ float fast_tanh(float x) {
    float e = __expf(2.0f * x), r;
    asm("rcp.approx.f32 %0, %1;" : "=f"(r) : "f"(e + 1.0f));
    return 1.0f - 2.0f * r;
}
__device__ __forceinline__ float fsigm(float x) {
    float e = __expf(-x), r;
    asm("rcp.approx.f32 %0, %1;" : "=f"(r) : "f"(e + 1.0f));
    return r;
}
__device__ __forceinline__ void split2(float v, __nv_bfloat16& hi, __nv_bfloat16& lo) {
    hi = __float2bfloat16(v);
    lo = __float2bfloat16(v - __bfloat162float(hi));
}
__device__ __forceinline__ uint32_t smem_u32(const void* p) {
    uint32_t a;
    asm("{ .reg .u64 t; cvta.to.shared.u64 t, %1; cvt.u32.u64 %0, t; }"
        : "=r"(a) : "l"(p));
    return a;
}
__device__ __forceinline__ void mma16816(float* d, const uint32_t* a, const uint32_t* b) {
    asm volatile(
        "mma.sync.aligned.m16n8k16.row.col.f32.bf16.bf16.f32 "
        "{%0,%1,%2,%3}, {%4,%5,%6,%7}, {%8,%9}, {%0,%1,%2,%3};"
        : "+f"(d[0]), "+f"(d[1]), "+f"(d[2]), "+f"(d[3])
        : "r"(a[0]), "r"(a[1]), "r"(a[2]), "r"(a[3]), "r"(b[0]), "r"(b[1]));
}
#define LDMX4(r0, r1, r2, r3, addr) \
    asm volatile("ldmatrix.sync.aligned.m8n8.x4.shared.b16 {%0,%1,%2,%3}, [%4];" \
        : "=r"(r0), "=r"(r1), "=r"(r2), "=r"(r3) : "r"(addr))
#define CP16(dst, src) \
    asm volatile("cp.async.cg.shared.global [%0], [%1], 16;" :: "r"(dst), "l"(src))
#define CP_COMMIT() asm volatile("cp.async.commit_group;" ::: "memory")
#define CP_WAIT(n)  asm volatile("cp.async.wait_group %0;" :: "n"(n) : "memory")

// ---------------- HMMA GEMM: C[M,N] = A'[M,K'] @ W'[N,K']^T (bf16->fp32) ------
#define BMM 128
#define BNN 128
#define BKC 32
#define SROWB 80                       // padded row: 40 bf16 = 80 bytes
#define BUFB  (128 * SROWB)            // 10240 bytes per stage buffer
#define WOFF  (3 * BUFB)               // Ws region offset
#define DSMEM (6 * BUFB)               // 61440 bytes

template<bool SPLIT>
__global__ void __launch_bounds__(128) mma_gemm(
    const __nv_bfloat16* __restrict__ A, int lda,
    const __nv_bfloat16* __restrict__ W, int ldw,
    const float* __restrict__ bias,
    float* __restrict__ C, int ldc,
    int chunks, int strideZ)
{
    extern __shared__ char dsm[];
    const uint32_t sbase = smem_u32(dsm);

    const int tid = threadIdx.x;
    const int wid = tid >> 5, lane = tid & 31;
    const int wm = wid & 1, wn = wid >> 1;
    const int g = lane >> 2, t4 = lane & 3;

    const int rowBase = blockIdx.x * BMM, colBase = blockIdx.y * BNN;
    const long kBase = (long)blockIdx.z * chunks * BKC;
    if (SPLIT) C += (size_t)blockIdx.z * strideZ;

    float acc[4][8][4];
#pragma unroll
    for (int i = 0; i < 4; i++)
#pragma unroll
        for (int j = 0; j < 8; j++)
#pragma unroll
            for (int v = 0; v < 4; v++) acc[i][j][v] = 0.0f;

    const int lrow = tid >> 2, lseg = tid & 3;
    const __nv_bfloat16* aSrc = A + (size_t)(rowBase + lrow) * lda + lseg * 8;
    const __nv_bfloat16* wSrc = W + (size_t)(colBase + lrow) * ldw + lseg * 8;
    const uint32_t aDst0 = sbase + lrow * SROWB + lseg * 16;
    const uint32_t wDst0 = sbase + WOFF + lrow * SROWB + lseg * 16;

    const int aFragRow = wm * 64 + (lane & 15);
    const uint32_t aFragB0 = sbase + aFragRow * SROWB + ((lane >> 4) << 4);
    const int bFragRow = wn * 64 + (((lane >> 4) << 3) | (lane & 7));
    const uint32_t bFragB0 = sbase + WOFF + bFragRow * SROWB + ((lane & 8) << 1);

    const int pre = (chunks < 2) ? chunks : 2;
    for (int i = 0; i < pre; i++) {
        const long k0 = kBase + (long)i * BKC;
#pragma unroll
        for (int p = 0; p < 4; p++) {
            CP16(aDst0 + i * BUFB + p * (32 * SROWB), (const void*)(aSrc + k0 + (size_t)p * 32 * lda));
            CP16(wDst0 + i * BUFB + p * (32 * SROWB), (const void*)(wSrc + k0 + (size_t)p * 32 * ldw));
        }
        CP_COMMIT();
    }

    for (int c = 0; c < chunks; ++c) {
        const int buf = c % 3;
        if (c + 2 < chunks) {
            const int nb = (c + 2) % 3;
            const long k0 = kBase + (long)(c + 2) * BKC;
#pragma unroll
            for (int p = 0; p < 4; p++) {
                CP16(aDst0 + nb * BUFB + p * (32 * SROWB), (const void*)(aSrc + k0 + (size_t)p * 32 * lda));
                CP16(wDst0 + nb * BUFB + p * (32 * SROWB), (const void*)(wSrc + k0 + (size_t)p * 32 * ldw));
            }
            CP_COMMIT();
            CP_WAIT(2);
        } else if (c + 1 < chunks) {
            CP_WAIT(1);
        } else {
            CP_WAIT(0);
        }
        __syncthreads();

#pragma unroll
        for (int ks = 0; ks < 2; ks++) {
            uint32_t af[4][4], bf[8][2];
#pragma unroll
            for (int mt = 0; mt < 4; mt++) {
                uint32_t addr = aFragB0 + buf * BUFB + mt * (16 * SROWB) + ks * 32;
                LDMX4(af[mt][0], af[mt][1], af[mt][2], af[mt][3], addr);
            }
#pragma unroll
            for (int nt = 0; nt < 4; nt++) {
                uint32_t addr = bFragB0 + buf * BUFB + nt * (16 * SROWB) + ks * 32;
                LDMX4(bf[2 * nt][0], bf[2 * nt][1], bf[2 * nt + 1][0], bf[2 * nt + 1][1], addr);
            }
#pragma unroll
            for (int mt = 0; mt < 4; mt++)
#pragma unroll
                for (int j = 0; j < 8; j++)
                    mma16816(acc[mt][j], af[mt], bf[j]);
        }
        __syncthreads();
    }

    const int row0 = rowBase + wm * 64;
    const int col0 = colBase + wn * 64;
#pragma unroll
    for (int mt = 0; mt < 4; mt++) {
#pragma unroll
        for (int j = 0; j < 8; j++) {
            const int r = row0 + mt * 16 + g;
            const int cc = col0 + j * 8 + 2 * t4;
            float2 v0 = make_float2(acc[mt][j][0], acc[mt][j][1]);
            float2 v1 = make_float2(acc[mt][j][2], acc[mt][j][3]);
            if (!SPLIT) {
                float2 bb = *(const float2*)(bias + cc);
                v0.x += bb.x; v0.y += bb.y;
                v1.x += bb.x; v1.y += bb.y;
            }
            *(float2*)(C + (size_t)r * ldc + cc) = v0;
            *(float2*)(C + (size_t)(r + 8) * ldc + cc) = v1;
        }
    }
}

// ---------------- setup: convert weights + nh, init state, zero out[0] ---------
#define S0 (H_ENC * H_ENC)
#define S1 (G4 * KX)
#define S2 (VOCAB * H_ENC)
#define S3 (NTOT * H_ENC)
__global__ void __launch_bounds__(256) k_setup(
    const float* __restrict__ W_att, const float* __restrict__ W_ih,
    const float* __restrict__ W_hh, const float* __restrict__ W_out,
    const float* __restrict__ nh,
    const float* __restrict__ b_ih, const float* __restrict__ b_hh,
    const int* __restrict__ root, const int* __restrict__ labels,
    const float* __restrict__ emb, float* __restrict__ out0)
{
    const int total = S0 + S1 + S2 + S3;
    int gid = blockIdx.x * blockDim.x + threadIdx.x;
    if (gid < G4) g_bg[gid] = b_ih[gid] + b_hh[gid];
    for (int i = gid; i < BV; i += gridDim.x * blockDim.x) out0[i] = 0.0f;

    if (gid < BATCH * H_ENC) {
        int b = gid >> 9, j = gid & 511;
        float h0 = nh[(size_t)root[b] * H_ENC + j];
        g_c[gid] = 0.0f;
        __nv_bfloat16 hi, lo;
        split2(h0, hi, lo);
        g_hb[b * KP_H + j] = hi; g_hb[b * KP_H + 512 + j] = hi; g_hb[b * KP_H + 1024 + j] = lo;
        g_xb[b * KP_X + 768 + j] = hi; g_xb[b * KP_X + 2048 + j] = hi; g_xb[b * KP_X + 3328 + j] = lo;
        if (gid < BATCH * H_DEC) {
            int be = gid >> 8, je = gid & 255;
            float e = emb[(size_t)labels[be] * H_DEC + je];
            split2(e, hi, lo);
            g_xb[be * KP_X + je] = hi; g_xb[be * KP_X + 1280 + je] = hi; g_xb[be * KP_X + 2560 + je] = lo;
        }
    }

    for (int idx = gid; idx < total; idx += gridDim.x * blockDim.x) {
        if (idx < S0) {
            int n = idx >> 9, k = idx & 511;
            __nv_bfloat16 hi, lo;
            split2(W_att[n * 1024 + k], hi, lo);       // W_att1 -> Wqo rows 0..511
            g_Wqo[(size_t)n * KP_H + k] = hi;
            g_Wqo[(size_t)n * KP_H + 512 + k] = lo;
            g_Wqo[(size_t)n * KP_H + 1024 + k] = hi;
            split2(W_att[n * 1024 + 512 + k], hi, lo); // W_att2 -> P weights
            g_Wab2[n * KP_H + k] = hi; g_Wab2[n * KP_H + 512 + k] = lo;
            g_Wab2[n * KP_H + 1024 + k] = hi;
        } else if (idx < S0 + S1) {
            int t = idx - S0;
            int n = t / KX, k = t - n * KX;
            float v = (k < 768) ? W_ih[n * 768 + k] : W_hh[n * 512 + (k - 768)];
            __nv_bfloat16 hi, lo;
            split2(v, hi, lo);
            g_Wgb[(size_t)n * KP_X + k] = hi;
            g_Wgb[(size_t)n * KP_X + 1280 + k] = lo;
            g_Wgb[(size_t)n * KP_X + 2560 + k] = hi;
        } else if (idx < S0 + S1 + S2) {
            int t = idx - S0 - S1;
            int n = t >> 9, k = t & 511;
            __nv_bfloat16 hi, lo;
            split2(W_out[(size_t)n * 512 + k], hi, lo); // W_out -> Wqo rows 512..
            g_Wqo[(size_t)(512 + n) * KP_H + k] = hi;
            g_Wqo[(size_t)(512 + n) * KP_H + 512 + k] = lo;
            g_Wqo[(size_t)(512 + n) * KP_H + 1024 + k] = hi;
        } else {
            int t = idx - S0 - S1 - S2;
            int n = t >> 9, k = t & 511;
            __nv_bfloat16 hi, lo;
            split2(nh[(size_t)n * 512 + k], hi, lo);
            g_nhb[(size_t)n * KP_H + k] = hi;
            g_nhb[(size_t)n * KP_H + 512 + k] = hi;
            g_nhb[(size_t)n * KP_H + 1024 + k] = lo;
        }
    }
}

// ---------------- k_score: e_n = exp(sum_j v[j]*tanh(P[n,j]+Qh[b,j])) ----------
// grid 512 = 128 segments x 4 node-slices; warp per node. No max pass:
// |score| <= ||v||_1 (~20), exp is fp32-safe; softmax is shift-invariant.
__global__ void __launch_bounds__(256) k_score(
    const int* __restrict__ root, const float* __restrict__ v_att)
{
    const int b = blockIdx.x >> 2, slice = blockIdx.x & 3;
    const int tid = threadIdx.x, lid = tid & 31, wid = tid >> 5;
    __shared__ float sQ[H_ENC], sV[H_ENC];

    const int s0 = root[b];
    const int s1 = (b == BATCH - 1) ? NTOT : root[b + 1];
    const int len = s1 - s0;
    const int a0 = s0 + (len * slice) / 4;
    const int a1 = s0 + (len * (slice + 1)) / 4;

    for (int j = tid; j < H_ENC; j += 256) {
        sQ[j] = g_qlP[(size_t)b * NQO + j] + g_qlP[PSTRIDE + (size_t)b * NQO + j];
        sV[j] = v_att[j];
    }
    __syncthreads();

    const float2* sQ2 = (const float2*)sQ;
    const float2* sV2 = (const float2*)sV;
    for (int n = a0 + wid; n < a1; n += 8) {
        const float2* Pr2 = (const float2*)(g_P + (size_t)n * H_ENC);
        float acc = 0.0f;
#pragma unroll
        for (int it = 0; it < 8; ++it) {
            int j = lid + it * 32;
            float2 p = Pr2[j], q = sQ2[j], vv = sV2[j];
            acc += vv.x * fast_tanh(p.x + q.x) + vv.y * fast_tanh(p.y + q.y);
        }
#pragma unroll
        for (int o = 16; o; o >>= 1) acc += __shfl_xor_sync(0xffffffffu, acc, o);
        if (lid == 0) g_score[n] = __expf(acc);
    }
}

// ---------------- k_attout2: attended (512 blocks) + out/argmax (128 blocks) ---
// blocks [0,512): (b = x>>2, colchunk = x&3): attended[b, chunk*128..+128)
//   each block deterministically re-reduces Z_b from e values (no atomics).
// blocks [512,640): logits reduce + slab + argmax + emb gather for b = x-512.
__global__ void __launch_bounds__(256) k_attout2(
    const float* __restrict__ nh, const int* __restrict__ root,
    const float* __restrict__ b_out, const float* __restrict__ emb,
    float* __restrict__ slabPrev, int doAtt, int doOut)
{
    const int tid = threadIdx.x;

    if (blockIdx.x < 512) {
        if (!doAtt) return;
        const int b = blockIdx.x >> 2, chunk = blockIdx.x & 3;
        const int s0 = root[b];
        const int s1 = (b == BATCH - 1) ? NTOT : root[b + 1];

        __shared__ float szred[8];
        __shared__ float s_invz;
        __shared__ float sacc[256];

        float z = 0.0f;
        for (int n = s0 + tid; n < s1; n += 256) z += g_score[n];
#pragma unroll
        for (int o = 16; o; o >>= 1) z += __shfl_xor_sync(0xffffffffu, z, o);
        if ((tid & 31) == 0) szred[tid >> 5] = z;
        __syncthreads();
        if (tid == 0) {
            float zz = 0.0f;
            for (int w = 0; w < 8; w++) zz += szred[w];
            s_invz = 1.0f / zz;
        }

        const int col = chunk * 128 + (tid & 127);
        const int par = tid >> 7;
        float acc = 0.0f;
        for (int n = s0 + par; n < s1; n += 2)
            acc += g_score[n] * nh[(size_t)n * H_ENC + col];
        sacc[tid] = acc;
        __syncthreads();
        if (tid < 128) {
            float a = (sacc[tid] + sacc[tid + 128]) * s_invz;
            __nv_bfloat16 hi, lo;
            split2(a, hi, lo);
            g_xb[b * KP_X + 256 + col] = hi;
            g_xb[b * KP_X + 1536 + col] = hi;
            g_xb[b * KP_X + 2816 + col] = lo;
        }
    } else {
        if (!doOut) return;
        const int b = blockIdx.x - 512;
        float* row = slabPrev + (size_t)b * VOCAB;
        float best = -3.402823466e38f;
        int bi = VOCAB;
        for (int j = tid; j < VOCAB; j += 256) {
            float v = b_out[j]
                + g_qlP[(size_t)b * NQO + H_ENC + j]
                + g_qlP[PSTRIDE + (size_t)b * NQO + H_ENC + j];
            row[j] = v;
            if (v > best) { best = v; bi = j; }
        }
        __shared__ float sv[256];
        __shared__ int si[256];
        __shared__ int s_cur;
        sv[tid] = best; si[tid] = bi;
        __syncthreads();
        for (int s = 128; s; s >>= 1) {
            if (tid < s) {
                float v2 = sv[tid + s]; int i2 = si[tid + s];
                if (v2 > sv[tid] || (v2 == sv[tid] && i2 < si[tid])) { sv[tid] = v2; si[tid] = i2; }
            }
            __syncthreads();
        }
        if (tid == 0) s_cur = si[0];
        __syncthreads();
        float e = emb[(size_t)s_cur * H_DEC + tid];   // H_DEC == 256 == blockDim
        __nv_bfloat16 hi, lo;
        split2(e, hi, lo);
        g_xb[b * KP_X + tid] = hi; g_xb[b * KP_X + 1280 + tid] = hi; g_xb[b * KP_X + 2560 + tid] = lo;
    }
}

// fused: gate partial-reduce + bias + LSTM update; writes h, c, and h slot of x
__global__ void __launch_bounds__(256) k_lstm() {
    const int idx = blockIdx.x * blockDim.x + threadIdx.x;   // 65536
    const int b = idx >> 9, j = idx & 511;
    float ig = g_bg[j], fg = g_bg[512 + j], gg = g_bg[1024 + j], og = g_bg[1536 + j];
#pragma unroll
    for (int z = 0; z < GT_SPLITS; z++) {
        const float* gr = g_gatesP + (size_t)z * (BATCH * G4) + b * G4 + j;
        ig += gr[0]; fg += gr[512]; gg += gr[1024]; og += gr[1536];
    }
    float c = fsigm(fg) * g_c[idx] + fsigm(ig) * fast_tanh(gg);
    g_c[idx] = c;
    float h = fsigm(og) * fast_tanh(c);
    __nv_bfloat16 hi, lo;
    split2(h, hi, lo);
    g_hb[b * KP_H + j] = hi; g_hb[b * KP_H + 512 + j] = hi; g_hb[b * KP_H + 1024 + j] = lo;
    g_xb[b * KP_X + 768 + j] = hi; g_xb[b * KP_X + 2048 + j] = hi; g_xb[b * KP_X + 3328 + j] = lo;
}

// ---------------- launch ----------------
extern "C" void kernel_launch(void* const* d_in, const int* in_sizes, int n_in,
                              void* d_out, int out_size) {
    const float* nh    = (const float*)d_in[0];
    const int*   labels= (const int*)  d_in[1];
    const int*   root  = (const int*)  d_in[2];
    const float* emb   = (const float*)d_in[3];
    const float* W_att = (const float*)d_in[4];
    const float* b_att = (const float*)d_in[5];
    const float* v_att = (const float*)d_in[6];
    const float* W_ih  = (const float*)d_in[7];
    const float* W_hh  = (const float*)d_in[8];
    const float* b_ih  = (const float*)d_in[9];
    const float* b_hh  = (const float*)d_in[10];
    const float* W_out = (const float*)d_in[11];
    const float* b_out = (const float*)d_in[12];
    float* out = (float*)d_out;

    float *pP, *pQlP, *pGatesP;
    __nv_bfloat16 *pHb, *pXb, *pNhb, *pWab2, *pWqo, *pWgb;
    cudaGetSymbolAddress((void**)&pP, g_P);
    cudaGetSymbolAddress((void**)&pQlP, g_qlP);
    cudaGetSymbolAddress((void**)&pGatesP, g_gatesP);
    cudaGetSymbolAddress((void**)&pHb, g_hb);
    cudaGetSymbolAddress((void**)&pXb, g_xb);
    cudaGetSymbolAddress((void**)&pNhb, g_nhb);
    cudaGetSymbolAddress((void**)&pWab2, g_Wab2);
    cudaGetSymbolAddress((void**)&pWqo, g_Wqo);
    cudaGetSymbolAddress((void**)&pWgb, g_Wgb);

    cudaFuncSetAttribute(mma_gemm<false>, cudaFuncAttributeMaxDynamicSharedMemorySize, DSMEM);
    cudaFuncSetAttribute(mma_gemm<true>,  cudaFuncAttributeMaxDynamicSharedMemorySize, DSMEM);

    // ---- setup (launch #4 = first k_score -> ncu -s 5 lands on it)
    k_setup<<<2048, 256>>>(W_att, W_ih, W_hh, W_out, nh, b_ih, b_hh,
                           root, labels, emb, out);
    // P = nh @ W_att[:,512:]^T + b_att   (step-invariant, fp32 out)
    mma_gemm<false><<<dim3(NTOT / 128, H_ENC / 128, 1), 128, DSMEM>>>(
        pNhb, KP_H, pWab2, KP_H, b_att, pP, H_ENC, KP_H / BKC, 0);
    // bootstrap [Qh1 | junk logits] from h0
    mma_gemm<true><<<dim3(1, NQO / 128, QL_SPLITS), 128, DSMEM>>>(
        pHb, KP_H, pWqo, KP_H, nullptr, pQlP, NQO,
        KP_H / BKC / QL_SPLITS, PSTRIDE);

    // ---- decode: score -> attout2 -> gates -> lstm -> [Qh|logits] GEMM ----
    for (int t = 1; t < LSEQ; t++) {
        float* slabPrev = (t > 1) ? (out + (size_t)(t - 1) * BV) : nullptr;
        k_score<<<512, 256>>>(root, v_att);
        k_attout2<<<640, 256>>>(nh, root, b_out, emb, slabPrev, 1, t > 1);
        // gates partials = x @ [W_ih|W_hh]^T
        mma_gemm<true><<<dim3(1, G4 / 128, GT_SPLITS), 128, DSMEM>>>(
            pXb, KP_X, pWgb, KP_X, nullptr, pGatesP, G4,
            KP_X / BKC / GT_SPLITS, BATCH * G4);
        k_lstm<<<256, 256>>>();
        // [Qh_{t+1} | logits_t] partials = h @ Wqo^T
        mma_gemm<true><<<dim3(1, NQO / 128, QL_SPLITS), 128, DSMEM>>>(
            pHb, KP_H, pWqo, KP_H, nullptr, pQlP, NQO,
            KP_H / BKC / QL_SPLITS, PSTRIDE);
    }
    // final out for step 12
    k_attout2<<<640, 256>>>(nh, root, b_out, emb,
                            out + (size_t)(LSEQ - 1) * BV, 0, 1);
}